// round 8
// baseline (speedup 1.0000x reference)
#include <cuda_runtime.h>
#include <cuda_fp16.h>
#include <cuda_bf16.h>
#include <math.h>

// Problem constants (fixed by the dataset)
#define NN 100000
#define NF 256
#define NH 16
#define NC 16
#define NE 3200000

#define SCAN_CHUNK 4096
#define SCAN_BLOCKS 25   // ceil(100000/4096)

#define NQUARTS (NE / 4)     // 800000 int4 groups
#define NOCTS   (NE / 8)     // 400000 8-edge groups

typedef unsigned long long u64;

// ---------------- device scratch (static, allowed) ----------------
__device__ int   g_cnt[NN];            // in-degree (no self loop)
__device__ int   g_rowstart[NN + 1];   // CSR row offsets (block-LOCAL scan)
__device__ int   g_rowfinal[NN + 1];   // CSR row offsets (final)
__device__ int   g_blocksums[SCAN_BLOCKS];
__device__ float g_dinv[NN];           // rsqrt(indeg+1)
__device__ float g_h[NN * NH];         // x@W1 (fp32, unscaled)
__device__ uint4 g_hh[NN * 2];         // fp16 (x@W1)*dinv : 16 halves/node
__device__ uint4 g_h1h[NN * 2];        // fp16 GCN output
__device__ int   g_srcsorted[NE];      // src ids grouped by dst
__device__ int   g_rank[NE];           // per-edge rank within its dst bucket

// ---------------- f32x2 helpers (FFMA2 is PTX-only) ----------------
__device__ __forceinline__ u64 pk2(float a, float b) {
    u64 r; asm("mov.b64 %0, {%1, %2};" : "=l"(r) : "f"(a), "f"(b)); return r;
}
__device__ __forceinline__ u64 dup2(float a) {
    u64 r; asm("mov.b64 %0, {%1, %1};" : "=l"(r) : "f"(a)); return r;
}
__device__ __forceinline__ u64 ffma2(u64 a, u64 b, u64 c) {
    u64 d; asm("fma.rn.f32x2 %0, %1, %2, %3;" : "=l"(d) : "l"(a), "l"(b), "l"(c)); return d;
}
__device__ __forceinline__ float2 unpk2(u64 a) {
    float2 f; asm("mov.b64 {%0, %1}, %2;" : "=f"(f.x), "=f"(f.y) : "l"(a)); return f;
}

// unpack a uint4 of 8 halves into 4 float2, accumulate
__device__ __forceinline__ void acc_h8(const uint4& v, float2& a0, float2& a1,
                                       float2& a2, float2& a3) {
    __half2 h0 = *reinterpret_cast<const __half2*>(&v.x);
    __half2 h1 = *reinterpret_cast<const __half2*>(&v.y);
    __half2 h2 = *reinterpret_cast<const __half2*>(&v.z);
    __half2 h3 = *reinterpret_cast<const __half2*>(&v.w);
    float2 f0 = __half22float2(h0), f1 = __half22float2(h1);
    float2 f2 = __half22float2(h2), f3 = __half22float2(h3);
    a0.x += f0.x; a0.y += f0.y; a1.x += f1.x; a1.y += f1.y;
    a2.x += f2.x; a2.y += f2.y; a3.x += f3.x; a3.y += f3.y;
}

__device__ __forceinline__ uint4 pack_h8(float2 a0, float2 a1, float2 a2, float2 a3) {
    __half2 h0 = __floats2half2_rn(a0.x, a0.y);
    __half2 h1 = __floats2half2_rn(a1.x, a1.y);
    __half2 h2 = __floats2half2_rn(a2.x, a2.y);
    __half2 h3 = __floats2half2_rn(a3.x, a3.y);
    uint4 o;
    o.x = *reinterpret_cast<unsigned*>(&h0);
    o.y = *reinterpret_cast<unsigned*>(&h1);
    o.z = *reinterpret_cast<unsigned*>(&h2);
    o.w = *reinterpret_cast<unsigned*>(&h3);
    return o;
}

#define RED8(mask, D)                                        \
    a0.x += __shfl_xor_sync(mask, a0.x, D);                  \
    a0.y += __shfl_xor_sync(mask, a0.y, D);                  \
    a1.x += __shfl_xor_sync(mask, a1.x, D);                  \
    a1.y += __shfl_xor_sync(mask, a1.y, D);                  \
    a2.x += __shfl_xor_sync(mask, a2.x, D);                  \
    a2.y += __shfl_xor_sync(mask, a2.y, D);                  \
    a3.x += __shfl_xor_sync(mask, a3.x, D);                  \
    a3.y += __shfl_xor_sync(mask, a3.y, D);

// ---------------- kernels ----------------

// histogram of dst + per-edge rank; 8 edges per thread (deep MLP)
__global__ void k_count(const int* __restrict__ dst) {
    int i = blockIdx.x * blockDim.x + threadIdx.x;   // i < NOCTS
    if (i >= NOCTS) return;
    int4 d0 = ((const int4*)dst)[2 * i];
    int4 d1 = ((const int4*)dst)[2 * i + 1];
    int4 r0, r1;
    r0.x = atomicAdd(&g_cnt[d0.x], 1);
    r0.y = atomicAdd(&g_cnt[d0.y], 1);
    r0.z = atomicAdd(&g_cnt[d0.z], 1);
    r0.w = atomicAdd(&g_cnt[d0.w], 1);
    r1.x = atomicAdd(&g_cnt[d1.x], 1);
    r1.y = atomicAdd(&g_cnt[d1.y], 1);
    r1.z = atomicAdd(&g_cnt[d1.z], 1);
    r1.w = atomicAdd(&g_cnt[d1.w], 1);
    ((int4*)g_rank)[2 * i]     = r0;
    ((int4*)g_rank)[2 * i + 1] = r1;
}

// per-block exclusive scan of g_cnt chunk -> g_rowstart (block-local), totals -> g_blocksums
__global__ void k_scan_local() {
    __shared__ int s[SCAN_CHUNK];
    __shared__ int tsum[256];
    int t = threadIdx.x;
    int base = blockIdx.x * SCAN_CHUNK;
    for (int i = t; i < SCAN_CHUNK; i += 256) {
        int idx = base + i;
        s[i] = (idx < NN) ? g_cnt[idx] : 0;
    }
    __syncthreads();

    int loc[16];
    int run = 0;
#pragma unroll
    for (int i = 0; i < 16; i++) {
        run += s[t * 16 + i];
        loc[i] = run;
    }
    tsum[t] = run;
    __syncthreads();
    for (int off = 1; off < 256; off <<= 1) {
        int v = (t >= off) ? tsum[t - off] : 0;
        __syncthreads();
        tsum[t] += v;
        __syncthreads();
    }
    int ex = (t == 0) ? 0 : tsum[t - 1];
#pragma unroll
    for (int i = 0; i < 16; i++) {
        s[t * 16 + i] = ex + (i ? loc[i - 1] : 0);
    }
    __syncthreads();
    for (int i = t; i < SCAN_CHUNK; i += 256) {
        int idx = base + i;
        if (idx < NN) g_rowstart[idx] = s[i];
    }
    if (t == 0) g_blocksums[blockIdx.x] = tsum[255];
}

// atomic-free CSR scatter; 8 edges per thread; local rowstart + smem block sums
__global__ void __launch_bounds__(256)
k_scatter(const int* __restrict__ src, const int* __restrict__ dst) {
    __shared__ int sbs[SCAN_BLOCKS + 1];
    int t = threadIdx.x;
    if (t <= SCAN_BLOCKS) {
        int acc = 0;
        for (int b = 0; b < t; b++) acc += g_blocksums[b];
        sbs[t] = acc;
    }
    __syncthreads();
    int i = blockIdx.x * 256 + t;   // i < NOCTS
    if (i >= NOCTS) return;
    int4 s0 = ((const int4*)src)[2 * i];
    int4 s1 = ((const int4*)src)[2 * i + 1];
    int4 d0 = ((const int4*)dst)[2 * i];
    int4 d1 = ((const int4*)dst)[2 * i + 1];
    int4 r0 = ((const int4*)g_rank)[2 * i];
    int4 r1 = ((const int4*)g_rank)[2 * i + 1];
    int q0 = __ldg(&g_rowstart[d0.x]);
    int q1 = __ldg(&g_rowstart[d0.y]);
    int q2 = __ldg(&g_rowstart[d0.z]);
    int q3 = __ldg(&g_rowstart[d0.w]);
    int q4 = __ldg(&g_rowstart[d1.x]);
    int q5 = __ldg(&g_rowstart[d1.y]);
    int q6 = __ldg(&g_rowstart[d1.z]);
    int q7 = __ldg(&g_rowstart[d1.w]);
    g_srcsorted[q0 + sbs[d0.x >> 12] + r0.x] = s0.x;
    g_srcsorted[q1 + sbs[d0.y >> 12] + r0.y] = s0.y;
    g_srcsorted[q2 + sbs[d0.z >> 12] + r0.z] = s0.z;
    g_srcsorted[q3 + sbs[d0.w >> 12] + r0.w] = s0.w;
    g_srcsorted[q4 + sbs[d1.x >> 12] + r1.x] = s1.x;
    g_srcsorted[q5 + sbs[d1.y >> 12] + r1.y] = s1.y;
    g_srcsorted[q6 + sbs[d1.z >> 12] + r1.z] = s1.z;
    g_srcsorted[q7 + sbs[d1.w >> 12] + r1.w] = s1.w;
}

// g_h[n,:] = x[n,:] @ W1   (UNscaled fp32 — no CSR dependency; 4 nodes/thread)
__global__ void __launch_bounds__(256)
k_gemm1(const float* __restrict__ x, const float* __restrict__ W1) {
    __shared__ float sW[NF * NH];   // 16 KB
    int t = threadIdx.x;
    for (int i = t; i < NF * NH; i += 256) sW[i] = W1[i];
    __syncthreads();

    int q = t & 3;
    int slot = t >> 2;
    int base = blockIdx.x * 256;
    int n0 = base + slot;
    int n1 = n0 + 64, n2 = n0 + 128, n3 = n0 + 192;
    int c0 = min(n0, NN - 1), c1 = min(n1, NN - 1);
    int c2 = min(n2, NN - 1), c3 = min(n3, NN - 1);

    const float4* x0 = (const float4*)(x + (size_t)c0 * NF);
    const float4* x1 = (const float4*)(x + (size_t)c1 * NF);
    const float4* x2 = (const float4*)(x + (size_t)c2 * NF);
    const float4* x3 = (const float4*)(x + (size_t)c3 * NF);
    const float4* w4 = (const float4*)sW;

    u64 a00 = 0, a01 = 0, a10 = 0, a11 = 0, a20 = 0, a21 = 0, a30 = 0, a31 = 0;

#define NODE_STEP(V, A0, A1)                                        \
    do {                                                            \
        u64 dx = dup2((V).x), dy = dup2((V).y);                     \
        u64 dz = dup2((V).z), dw = dup2((V).w);                     \
        A0 = ffma2(dx, w0a, A0); A1 = ffma2(dx, w0b, A1);           \
        A0 = ffma2(dy, w1a, A0); A1 = ffma2(dy, w1b, A1);           \
        A0 = ffma2(dz, w2a, A0); A1 = ffma2(dz, w2b, A1);           \
        A0 = ffma2(dw, w3a, A0); A1 = ffma2(dw, w3b, A1);           \
    } while (0)

#pragma unroll 4
    for (int kk = 0; kk < 64; kk++) {
        float4 v0 = __ldcs(&x0[kk]);
        float4 v1 = __ldcs(&x1[kk]);
        float4 v2 = __ldcs(&x2[kk]);
        float4 v3 = __ldcs(&x3[kk]);
        int kb = kk * 16 + q;
        float4 w0 = w4[kb];
        float4 w1 = w4[kb + 4];
        float4 w2 = w4[kb + 8];
        float4 w3 = w4[kb + 12];
        u64 w0a = pk2(w0.x, w0.y), w0b = pk2(w0.z, w0.w);
        u64 w1a = pk2(w1.x, w1.y), w1b = pk2(w1.z, w1.w);
        u64 w2a = pk2(w2.x, w2.y), w2b = pk2(w2.z, w2.w);
        u64 w3a = pk2(w3.x, w3.y), w3b = pk2(w3.z, w3.w);
        NODE_STEP(v0, a00, a01);
        NODE_STEP(v1, a10, a11);
        NODE_STEP(v2, a20, a21);
        NODE_STEP(v3, a30, a31);
    }
#undef NODE_STEP

    {
        int ns[4] = {n0, n1, n2, n3};
        u64 lo[4] = {a00, a10, a20, a30};
        u64 hi[4] = {a01, a11, a21, a31};
#pragma unroll
        for (int j = 0; j < 4; j++) {
            int n = ns[j];
            if (n < NN) {
                float2 l = unpk2(lo[j]), h = unpk2(hi[j]);
                *(float4*)&g_h[n * NH + q * 4] = make_float4(l.x, l.y, h.x, h.y);
            }
        }
    }
}

// merged fixup+scale: rowfinal, dinv, and fp16 conversion of g_h*dinv.
// thread i handles half-row p of node n (dinv recomputed locally: no dep).
__global__ void k_finish() {
    __shared__ int sbs[SCAN_BLOCKS];
    int t = threadIdx.x;
    if (t < SCAN_BLOCKS) sbs[t] = g_blocksums[t];
    __syncthreads();
    int i = blockIdx.x * 256 + t;   // i < NN*2
    if (i >= NN * 2) return;
    int n = i >> 1, p = i & 1;
    float dv = rsqrtf((float)(g_cnt[n] + 1));
    if (p == 0) {
        int chunk = n >> 12;
        int off = 0;
        for (int b = 0; b < chunk; b++) off += sbs[b];
        g_rowfinal[n] = g_rowstart[n] + off;
        g_dinv[n] = dv;
        if (n == 0) g_rowfinal[NN] = NE;
    }
    const float4* r = (const float4*)&g_h[n * NH + p * 8];
    float4 a = r[0], b = r[1];
    g_hh[i] = pack_h8(make_float2(a.x * dv, a.y * dv), make_float2(a.z * dv, a.w * dv),
                      make_float2(b.x * dv, b.y * dv), make_float2(b.z * dv, b.w * dv));
}

// GCN aggregate (fp16, batched idx + shfl): one warp per node.
// Each lane loads srcsorted[start+lane] (coalesced 128B); indices distributed
// via shfl; each lane issues 2 independent feature loads per 32-edge batch.
__global__ void k_gcn(const float* __restrict__ b1) {
    int gw = (blockIdx.x * blockDim.x + threadIdx.x) >> 5;
    int lane = threadIdx.x & 31;
    if (gw >= NN) return;
    int n = gw;
    int start = __ldg(&g_rowfinal[n]);
    int end   = __ldg(&g_rowfinal[n + 1]);
    int grp = lane >> 1, q = lane & 1;

    float2 a0 = {0, 0}, a1 = {0, 0}, a2 = {0, 0}, a3 = {0, 0};
    for (int base = start; base < end; base += 32) {
        int j = base + lane;
        int myidx = (j < end) ? __ldg(&g_srcsorted[j]) : 0;
#pragma unroll
        for (int p = 0; p < 2; p++) {
            int e = base + p * 16 + grp;
            int s = __shfl_sync(0xffffffffu, myidx, p * 16 + grp);
            if (e < end) {
                uint4 v = __ldg(&g_hh[s * 2 + q]);
                acc_h8(v, a0, a1, a2, a3);
            }
        }
    }
    RED8(0xffffffffu, 2); RED8(0xffffffffu, 4);
    RED8(0xffffffffu, 8); RED8(0xffffffffu, 16);

    if (lane < 2) {
        uint4 sv = g_hh[n * 2 + lane];
        float2 s0 = {0, 0}, s1 = {0, 0}, s2 = {0, 0}, s3 = {0, 0};
        acc_h8(sv, s0, s1, s2, s3);
        float dv = g_dinv[n];
        const float4* b4 = (const float4*)b1;
        float4 bA = __ldg(&b4[lane * 2]), bB = __ldg(&b4[lane * 2 + 1]);
        float2 r0 = {(a0.x + s0.x) * dv + bA.x, (a0.y + s0.y) * dv + bA.y};
        float2 r1 = {(a1.x + s1.x) * dv + bA.z, (a1.y + s1.y) * dv + bA.w};
        float2 r2 = {(a2.x + s2.x) * dv + bB.x, (a2.y + s2.y) * dv + bB.y};
        float2 r3 = {(a3.x + s3.x) * dv + bB.z, (a3.y + s3.y) * dv + bB.w};
        g_h1h[n * 2 + lane] = pack_h8(r0, r1, r2, r3);
    }
}

// SAGE (fp16, batched idx + shfl): agg = mean h1[src]; out = agg@Wl + h1@Wr + b2; log_softmax
__global__ void k_sage(const float* __restrict__ Wl, const float* __restrict__ Wr,
                       const float* __restrict__ b2, float* __restrict__ out) {
    __shared__ float sWl[NH * NC], sWr[NH * NC], sB2[NC];
    __shared__ float sAgg[8][16], sH1[8][16];
    int t = threadIdx.x;
    for (int i = t; i < NH * NC; i += 256) { sWl[i] = Wl[i]; sWr[i] = Wr[i]; }
    if (t < NC) sB2[t] = b2[t];
    __syncthreads();

    int wib = t >> 5, lane = t & 31;
    int n = blockIdx.x * 8 + wib;
    if (n >= NN) return;

    int start = __ldg(&g_rowfinal[n]);
    int end   = __ldg(&g_rowfinal[n + 1]);
    int grp = lane >> 1, q = lane & 1;

    float2 a0 = {0, 0}, a1 = {0, 0}, a2 = {0, 0}, a3 = {0, 0};
    for (int base = start; base < end; base += 32) {
        int j = base + lane;
        int myidx = (j < end) ? __ldg(&g_srcsorted[j]) : 0;
#pragma unroll
        for (int p = 0; p < 2; p++) {
            int e = base + p * 16 + grp;
            int s = __shfl_sync(0xffffffffu, myidx, p * 16 + grp);
            if (e < end) {
                uint4 v = __ldg(&g_h1h[s * 2 + q]);
                acc_h8(v, a0, a1, a2, a3);
            }
        }
    }
    RED8(0xffffffffu, 2); RED8(0xffffffffu, 4);
    RED8(0xffffffffu, 8); RED8(0xffffffffu, 16);

    if (lane < 2) {
        float inv = 1.0f / fmaxf((float)(end - start), 1.0f);
        float* ag = &sAgg[wib][lane * 8];
        ag[0] = a0.x * inv; ag[1] = a0.y * inv; ag[2] = a1.x * inv; ag[3] = a1.y * inv;
        ag[4] = a2.x * inv; ag[5] = a2.y * inv; ag[6] = a3.x * inv; ag[7] = a3.y * inv;
        uint4 hv = g_h1h[n * 2 + lane];
        float2 h0 = {0, 0}, h1 = {0, 0}, h2 = {0, 0}, h3 = {0, 0};
        acc_h8(hv, h0, h1, h2, h3);
        float* hh = &sH1[wib][lane * 8];
        hh[0] = h0.x; hh[1] = h0.y; hh[2] = h1.x; hh[3] = h1.y;
        hh[4] = h2.x; hh[5] = h2.y; hh[6] = h3.x; hh[7] = h3.y;
    }
    __syncwarp();
    if (lane < 16) {
        float o = sB2[lane];
#pragma unroll
        for (int k = 0; k < 16; k++) {
            o += sAgg[wib][k] * sWl[k * NC + lane] + sH1[wib][k] * sWr[k * NC + lane];
        }
        float m = o;
#pragma unroll
        for (int d = 8; d >= 1; d >>= 1)
            m = fmaxf(m, __shfl_xor_sync(0xffffu, m, d));
        float e = __expf(o - m);
        float ssum = e;
#pragma unroll
        for (int d = 8; d >= 1; d >>= 1)
            ssum += __shfl_xor_sync(0xffffu, ssum, d);
        out[n * NC + lane] = (o - m) - __logf(ssum);
    }
}

// ---------------- launch (fork-join two-stream graph) ----------------
static cudaStream_t s2 = nullptr;
static cudaEvent_t evFork = nullptr, evScan = nullptr, evSide = nullptr;

extern "C" void kernel_launch(void* const* d_in, const int* in_sizes, int n_in,
                              void* d_out, int out_size) {
    const float* x  = (const float*)d_in[0];
    const int*   ei = (const int*)d_in[1];
    const float* W1 = (const float*)d_in[2];
    const float* b1 = (const float*)d_in[3];
    const float* Wl = (const float*)d_in[4];
    const float* Wr = (const float*)d_in[5];
    const float* b2 = (const float*)d_in[6];
    float* out = (float*)d_out;

    const int* src = ei;
    const int* dst = ei + NE;

    if (!s2) {
        cudaStreamCreateWithFlags(&s2, cudaStreamNonBlocking);
        cudaEventCreateWithFlags(&evFork, cudaEventDisableTiming);
        cudaEventCreateWithFlags(&evScan, cudaEventDisableTiming);
        cudaEventCreateWithFlags(&evSide, cudaEventDisableTiming);
    }

    void* cnt_ptr = nullptr;
    cudaGetSymbolAddress(&cnt_ptr, g_cnt);

    // fork: side stream runs gemm (no CSR deps) concurrently with CSR build
    cudaEventRecord(evFork, 0);
    cudaStreamWaitEvent(s2, evFork, 0);
    k_gemm1<<<(NN + 255) / 256, 256, 0, s2>>>(x, W1);

    // main stream: CSR build
    cudaMemsetAsync(cnt_ptr, 0, NN * sizeof(int), 0);
    k_count<<<(NOCTS + 255) / 256, 256>>>(dst);
    k_scan_local<<<SCAN_BLOCKS, 256>>>();
    cudaEventRecord(evScan, 0);
    k_scatter<<<(NOCTS + 255) / 256, 256>>>(src, dst);

    // side stream: rowfinal + dinv + fp16 scale (overlaps scatter)
    cudaStreamWaitEvent(s2, evScan, 0);
    k_finish<<<(NN * 2 + 255) / 256, 256, 0, s2>>>();
    cudaEventRecord(evSide, s2);

    // join, then aggregations
    cudaStreamWaitEvent(0, evSide, 0);
    k_gcn<<<(NN * 32 + 255) / 256, 256>>>(b1);
    k_sage<<<(NN * 32 + 255) / 256, 256>>>(Wl, Wr, b2, out);
}

// round 9
// speedup vs baseline: 1.0301x; 1.0301x over previous
#include <cuda_runtime.h>
#include <cuda_bf16.h>
#include <math.h>

// Problem constants (fixed by the dataset)
#define NN 100000
#define NF 256
#define NH 16
#define NC 16
#define NE 3200000

#define SCAN_CHUNK 4096
#define SCAN_BLOCKS 25   // ceil(100000/4096)
#define NOCTS   (NE / 8)     // 400000 8-edge groups

typedef unsigned long long u64;

// ---------------- device scratch (static, allowed) ----------------
__device__ int   g_cnt[NN];            // in-degree (no self loop)
__device__ int   g_rowstart[NN + 1];   // CSR row offsets (block-LOCAL scan)
__device__ int   g_rowfinal[NN + 1];   // CSR row offsets (final)
__device__ int   g_blocksums[SCAN_BLOCKS];
__device__ float g_dinv[NN];           // rsqrt(indeg+1)
__device__ float g_h[NN * NH];         // x@W1, scaled by dinv in k_finish
__device__ float g_h1[NN * NH];        // GCN output
__device__ int   g_srcsorted[NE];      // src ids grouped by dst
__device__ int   g_rank[NE];           // per-edge rank within its dst bucket

// ---------------- f32x2 helpers (FFMA2 is PTX-only) ----------------
__device__ __forceinline__ u64 pk2(float a, float b) {
    u64 r; asm("mov.b64 %0, {%1, %2};" : "=l"(r) : "f"(a), "f"(b)); return r;
}
__device__ __forceinline__ u64 dup2(float a) {
    u64 r; asm("mov.b64 %0, {%1, %1};" : "=l"(r) : "f"(a)); return r;
}
__device__ __forceinline__ u64 ffma2(u64 a, u64 b, u64 c) {
    u64 d; asm("fma.rn.f32x2 %0, %1, %2, %3;" : "=l"(d) : "l"(a), "l"(b), "l"(c)); return d;
}
__device__ __forceinline__ float2 unpk2(u64 a) {
    float2 f; asm("mov.b64 {%0, %1}, %2;" : "=f"(f.x), "=f"(f.y) : "l"(a)); return f;
}

// ---------------- kernels ----------------

// histogram of dst + per-edge rank; 8 edges per thread
__global__ void k_count(const int* __restrict__ dst) {
    int i = blockIdx.x * blockDim.x + threadIdx.x;   // i < NOCTS
    if (i >= NOCTS) return;
    int4 d0 = ((const int4*)dst)[2 * i];
    int4 d1 = ((const int4*)dst)[2 * i + 1];
    int4 r0, r1;
    r0.x = atomicAdd(&g_cnt[d0.x], 1);
    r0.y = atomicAdd(&g_cnt[d0.y], 1);
    r0.z = atomicAdd(&g_cnt[d0.z], 1);
    r0.w = atomicAdd(&g_cnt[d0.w], 1);
    r1.x = atomicAdd(&g_cnt[d1.x], 1);
    r1.y = atomicAdd(&g_cnt[d1.y], 1);
    r1.z = atomicAdd(&g_cnt[d1.z], 1);
    r1.w = atomicAdd(&g_cnt[d1.w], 1);
    ((int4*)g_rank)[2 * i]     = r0;
    ((int4*)g_rank)[2 * i + 1] = r1;
}

// per-block exclusive scan of g_cnt chunk -> g_rowstart (block-local), totals -> g_blocksums
__global__ void k_scan_local() {
    __shared__ int s[SCAN_CHUNK];
    __shared__ int tsum[256];
    int t = threadIdx.x;
    int base = blockIdx.x * SCAN_CHUNK;
    for (int i = t; i < SCAN_CHUNK; i += 256) {
        int idx = base + i;
        s[i] = (idx < NN) ? g_cnt[idx] : 0;
    }
    __syncthreads();

    int loc[16];
    int run = 0;
#pragma unroll
    for (int i = 0; i < 16; i++) {
        run += s[t * 16 + i];
        loc[i] = run;
    }
    tsum[t] = run;
    __syncthreads();
    for (int off = 1; off < 256; off <<= 1) {
        int v = (t >= off) ? tsum[t - off] : 0;
        __syncthreads();
        tsum[t] += v;
        __syncthreads();
    }
    int ex = (t == 0) ? 0 : tsum[t - 1];
#pragma unroll
    for (int i = 0; i < 16; i++) {
        s[t * 16 + i] = ex + (i ? loc[i - 1] : 0);
    }
    __syncthreads();
    for (int i = t; i < SCAN_CHUNK; i += 256) {
        int idx = base + i;
        if (idx < NN) g_rowstart[idx] = s[i];
    }
    if (t == 0) g_blocksums[blockIdx.x] = tsum[255];
}

// atomic-free CSR scatter; 8 edges per thread; local rowstart + smem block sums
__global__ void __launch_bounds__(256)
k_scatter(const int* __restrict__ src, const int* __restrict__ dst) {
    __shared__ int sbs[SCAN_BLOCKS + 1];
    int t = threadIdx.x;
    if (t <= SCAN_BLOCKS) {
        int acc = 0;
        for (int b = 0; b < t; b++) acc += g_blocksums[b];
        sbs[t] = acc;
    }
    __syncthreads();
    int i = blockIdx.x * 256 + t;   // i < NOCTS
    if (i >= NOCTS) return;
    int4 s0 = ((const int4*)src)[2 * i];
    int4 s1 = ((const int4*)src)[2 * i + 1];
    int4 d0 = ((const int4*)dst)[2 * i];
    int4 d1 = ((const int4*)dst)[2 * i + 1];
    int4 r0 = ((const int4*)g_rank)[2 * i];
    int4 r1 = ((const int4*)g_rank)[2 * i + 1];
    int q0 = __ldg(&g_rowstart[d0.x]);
    int q1 = __ldg(&g_rowstart[d0.y]);
    int q2 = __ldg(&g_rowstart[d0.z]);
    int q3 = __ldg(&g_rowstart[d0.w]);
    int q4 = __ldg(&g_rowstart[d1.x]);
    int q5 = __ldg(&g_rowstart[d1.y]);
    int q6 = __ldg(&g_rowstart[d1.z]);
    int q7 = __ldg(&g_rowstart[d1.w]);
    g_srcsorted[q0 + sbs[d0.x >> 12] + r0.x] = s0.x;
    g_srcsorted[q1 + sbs[d0.y >> 12] + r0.y] = s0.y;
    g_srcsorted[q2 + sbs[d0.z >> 12] + r0.z] = s0.z;
    g_srcsorted[q3 + sbs[d0.w >> 12] + r0.w] = s0.w;
    g_srcsorted[q4 + sbs[d1.x >> 12] + r1.x] = s1.x;
    g_srcsorted[q5 + sbs[d1.y >> 12] + r1.y] = s1.y;
    g_srcsorted[q6 + sbs[d1.z >> 12] + r1.z] = s1.z;
    g_srcsorted[q7 + sbs[d1.w >> 12] + r1.w] = s1.w;
}

// g_h[n,:] = x[n,:] @ W1   (UNscaled fp32 — no CSR dependency; 4 nodes/thread)
__global__ void __launch_bounds__(256)
k_gemm1(const float* __restrict__ x, const float* __restrict__ W1) {
    __shared__ float sW[NF * NH];   // 16 KB
    int t = threadIdx.x;
    for (int i = t; i < NF * NH; i += 256) sW[i] = W1[i];
    __syncthreads();

    int q = t & 3;
    int slot = t >> 2;
    int base = blockIdx.x * 256;
    int n0 = base + slot;
    int n1 = n0 + 64, n2 = n0 + 128, n3 = n0 + 192;
    int c0 = min(n0, NN - 1), c1 = min(n1, NN - 1);
    int c2 = min(n2, NN - 1), c3 = min(n3, NN - 1);

    const float4* x0 = (const float4*)(x + (size_t)c0 * NF);
    const float4* x1 = (const float4*)(x + (size_t)c1 * NF);
    const float4* x2 = (const float4*)(x + (size_t)c2 * NF);
    const float4* x3 = (const float4*)(x + (size_t)c3 * NF);
    const float4* w4 = (const float4*)sW;

    u64 a00 = 0, a01 = 0, a10 = 0, a11 = 0, a20 = 0, a21 = 0, a30 = 0, a31 = 0;

#define NODE_STEP(V, A0, A1)                                        \
    do {                                                            \
        u64 dx = dup2((V).x), dy = dup2((V).y);                     \
        u64 dz = dup2((V).z), dw = dup2((V).w);                     \
        A0 = ffma2(dx, w0a, A0); A1 = ffma2(dx, w0b, A1);           \
        A0 = ffma2(dy, w1a, A0); A1 = ffma2(dy, w1b, A1);           \
        A0 = ffma2(dz, w2a, A0); A1 = ffma2(dz, w2b, A1);           \
        A0 = ffma2(dw, w3a, A0); A1 = ffma2(dw, w3b, A1);           \
    } while (0)

#pragma unroll 4
    for (int kk = 0; kk < 64; kk++) {
        float4 v0 = __ldcs(&x0[kk]);
        float4 v1 = __ldcs(&x1[kk]);
        float4 v2 = __ldcs(&x2[kk]);
        float4 v3 = __ldcs(&x3[kk]);
        int kb = kk * 16 + q;
        float4 w0 = w4[kb];
        float4 w1 = w4[kb + 4];
        float4 w2 = w4[kb + 8];
        float4 w3 = w4[kb + 12];
        u64 w0a = pk2(w0.x, w0.y), w0b = pk2(w0.z, w0.w);
        u64 w1a = pk2(w1.x, w1.y), w1b = pk2(w1.z, w1.w);
        u64 w2a = pk2(w2.x, w2.y), w2b = pk2(w2.z, w2.w);
        u64 w3a = pk2(w3.x, w3.y), w3b = pk2(w3.z, w3.w);
        NODE_STEP(v0, a00, a01);
        NODE_STEP(v1, a10, a11);
        NODE_STEP(v2, a20, a21);
        NODE_STEP(v3, a30, a31);
    }
#undef NODE_STEP

    {
        int ns[4] = {n0, n1, n2, n3};
        u64 lo[4] = {a00, a10, a20, a30};
        u64 hi[4] = {a01, a11, a21, a31};
#pragma unroll
        for (int j = 0; j < 4; j++) {
            int n = ns[j];
            if (n < NN) {
                float2 l = unpk2(lo[j]), h = unpk2(hi[j]);
                *(float4*)&g_h[n * NH + q * 4] = make_float4(l.x, l.y, h.x, h.y);
            }
        }
    }
}

// merged fixup + scale: rowfinal, dinv, and in-place g_h *= dinv (fp32).
// thread i handles quarter-row p of node n (dinv recomputed locally: no dep).
__global__ void k_finish() {
    __shared__ int sbs[SCAN_BLOCKS];
    int t = threadIdx.x;
    if (t < SCAN_BLOCKS) sbs[t] = g_blocksums[t];
    __syncthreads();
    int i = blockIdx.x * 256 + t;   // i < NN*4
    if (i >= NN * 4) return;
    int n = i >> 2, p = i & 3;
    float dv = rsqrtf((float)(g_cnt[n] + 1));
    if (p == 0) {
        int chunk = n >> 12;
        int off = 0;
        for (int b = 0; b < chunk; b++) off += sbs[b];
        g_rowfinal[n] = g_rowstart[n] + off;
        g_dinv[n] = dv;
        if (n == 0) g_rowfinal[NN] = NE;
    }
    float4 v = *(float4*)&g_h[i * 4];
    v.x *= dv; v.y *= dv; v.z *= dv; v.w *= dv;
    *(float4*)&g_h[i * 4] = v;
}

// GCN aggregate: h1[n] = dinv[n] * (sum_{in-edges} g_h[src] + g_h[n]) + b1
// one warp per node; 8 edge-slots x 4 lanes (each lane handles a c-quad)  [R6-best]
__global__ void k_gcn(const float* __restrict__ b1) {
    int gw = (blockIdx.x * blockDim.x + threadIdx.x) >> 5;
    int lane = threadIdx.x & 31;
    if (gw >= NN) return;
    int n = gw;
    int start = __ldg(&g_rowfinal[n]);
    int end   = __ldg(&g_rowfinal[n + 1]);
    int grp = lane >> 2, q = lane & 3;

    float4 acc = make_float4(0.f, 0.f, 0.f, 0.f);
    for (int j = start + grp; j < end; j += 8) {
        int s = __ldg(&g_srcsorted[j]);
        float4 v = __ldg((const float4*)&g_h[s * NH + q * 4]);
        acc.x += v.x; acc.y += v.y; acc.z += v.z; acc.w += v.w;
    }
#pragma unroll
    for (int d = 4; d < 32; d <<= 1) {
        acc.x += __shfl_xor_sync(0xffffffffu, acc.x, d);
        acc.y += __shfl_xor_sync(0xffffffffu, acc.y, d);
        acc.z += __shfl_xor_sync(0xffffffffu, acc.z, d);
        acc.w += __shfl_xor_sync(0xffffffffu, acc.w, d);
    }
    if (lane < 4) {
        float4 self = *(const float4*)&g_h[n * NH + lane * 4];
        float dv = g_dinv[n];
        float4 bb = __ldg((const float4*)&b1[lane * 4]);
        float4 r;
        r.x = (acc.x + self.x) * dv + bb.x;
        r.y = (acc.y + self.y) * dv + bb.y;
        r.z = (acc.z + self.z) * dv + bb.z;
        r.w = (acc.w + self.w) * dv + bb.w;
        *(float4*)&g_h1[n * NH + lane * 4] = r;
    }
}

// SAGE: agg = mean h1[src]; out = agg@Wl + h1[n]@Wr + b2; log_softmax  [R6-best]
__global__ void k_sage(const float* __restrict__ Wl, const float* __restrict__ Wr,
                       const float* __restrict__ b2, float* __restrict__ out) {
    __shared__ float sWl[NH * NC], sWr[NH * NC], sB2[NC];
    __shared__ float sAgg[8][16], sH1[8][16];
    int t = threadIdx.x;
    for (int i = t; i < NH * NC; i += 256) { sWl[i] = Wl[i]; sWr[i] = Wr[i]; }
    if (t < NC) sB2[t] = b2[t];
    __syncthreads();

    int wib = t >> 5, lane = t & 31;
    int n = blockIdx.x * 8 + wib;
    if (n >= NN) return;

    int start = __ldg(&g_rowfinal[n]);
    int end   = __ldg(&g_rowfinal[n + 1]);
    int grp = lane >> 2, q = lane & 3;

    float4 acc = make_float4(0.f, 0.f, 0.f, 0.f);
    for (int j = start + grp; j < end; j += 8) {
        int s = __ldg(&g_srcsorted[j]);
        float4 v = __ldg((const float4*)&g_h1[s * NH + q * 4]);
        acc.x += v.x; acc.y += v.y; acc.z += v.z; acc.w += v.w;
    }
#pragma unroll
    for (int d = 4; d < 32; d <<= 1) {
        acc.x += __shfl_xor_sync(0xffffffffu, acc.x, d);
        acc.y += __shfl_xor_sync(0xffffffffu, acc.y, d);
        acc.z += __shfl_xor_sync(0xffffffffu, acc.z, d);
        acc.w += __shfl_xor_sync(0xffffffffu, acc.w, d);
    }
    float inv = 1.0f / fmaxf((float)(end - start), 1.0f);
    if (lane < 4) {
        float4 a;
        a.x = acc.x * inv; a.y = acc.y * inv; a.z = acc.z * inv; a.w = acc.w * inv;
        *(float4*)&sAgg[wib][lane * 4] = a;
        float4 h1v = *(const float4*)&g_h1[n * NH + lane * 4];
        *(float4*)&sH1[wib][lane * 4] = h1v;
    }
    __syncwarp();
    if (lane < 16) {
        float o = sB2[lane];
#pragma unroll
        for (int k = 0; k < 16; k++) {
            o += sAgg[wib][k] * sWl[k * NC + lane] + sH1[wib][k] * sWr[k * NC + lane];
        }
        float m = o;
#pragma unroll
        for (int d = 8; d >= 1; d >>= 1)
            m = fmaxf(m, __shfl_xor_sync(0xffffu, m, d));
        float e = __expf(o - m);
        float ssum = e;
#pragma unroll
        for (int d = 8; d >= 1; d >>= 1)
            ssum += __shfl_xor_sync(0xffffu, ssum, d);
        out[n * NC + lane] = (o - m) - __logf(ssum);
    }
}

// ---------------- launch (fork-join two-stream graph) ----------------
static cudaStream_t s2 = nullptr;
static cudaEvent_t evFork = nullptr, evScan = nullptr, evSide = nullptr;

extern "C" void kernel_launch(void* const* d_in, const int* in_sizes, int n_in,
                              void* d_out, int out_size) {
    const float* x  = (const float*)d_in[0];
    const int*   ei = (const int*)d_in[1];
    const float* W1 = (const float*)d_in[2];
    const float* b1 = (const float*)d_in[3];
    const float* Wl = (const float*)d_in[4];
    const float* Wr = (const float*)d_in[5];
    const float* b2 = (const float*)d_in[6];
    float* out = (float*)d_out;

    const int* src = ei;
    const int* dst = ei + NE;

    if (!s2) {
        cudaStreamCreateWithFlags(&s2, cudaStreamNonBlocking);
        cudaEventCreateWithFlags(&evFork, cudaEventDisableTiming);
        cudaEventCreateWithFlags(&evScan, cudaEventDisableTiming);
        cudaEventCreateWithFlags(&evSide, cudaEventDisableTiming);
    }

    void* cnt_ptr = nullptr;
    cudaGetSymbolAddress(&cnt_ptr, g_cnt);

    // fork: side stream runs gemm (no CSR deps) concurrently with CSR build
    cudaEventRecord(evFork, 0);
    cudaStreamWaitEvent(s2, evFork, 0);
    k_gemm1<<<(NN + 255) / 256, 256, 0, s2>>>(x, W1);

    // main stream: CSR build
    cudaMemsetAsync(cnt_ptr, 0, NN * sizeof(int), 0);
    k_count<<<(NOCTS + 255) / 256, 256>>>(dst);
    k_scan_local<<<SCAN_BLOCKS, 256>>>();
    cudaEventRecord(evScan, 0);
    k_scatter<<<(NOCTS + 255) / 256, 256>>>(src, dst);

    // side stream: rowfinal + dinv + in-place scale (overlaps scatter)
    cudaStreamWaitEvent(s2, evScan, 0);
    k_finish<<<(NN * 4 + 255) / 256, 256, 0, s2>>>();
    cudaEventRecord(evSide, s2);

    // join, then aggregations
    cudaStreamWaitEvent(0, evSide, 0);
    k_gcn<<<(NN * 32 + 255) / 256, 256>>>(b1);
    k_sage<<<(NN * 32 + 255) / 256, 256>>>(Wl, Wr, b2, out);
}

// round 10
// speedup vs baseline: 1.0423x; 1.0118x over previous
#include <cuda_runtime.h>
#include <cuda_bf16.h>
#include <math.h>

// Problem constants (fixed by the dataset)
#define NN 100000
#define NF 256
#define NH 16
#define NC 16
#define NE 3200000

#define SCAN_CHUNK 4096
#define SCAN_BLOCKS 25   // ceil(100000/4096)
#define NOCTS   (NE / 8)     // 400000 8-edge groups

typedef unsigned long long u64;

// ---------------- device scratch (static, allowed) ----------------
__device__ int   g_cnt[NN];            // in-degree (no self loop)
__device__ int   g_rowstart[NN + 1];   // CSR row offsets (block-LOCAL scan)
__device__ int   g_rowfinal[NN + 1];   // CSR row offsets (final)
__device__ int   g_blocksums[SCAN_BLOCKS];
__device__ float g_dinv[NN];           // rsqrt(indeg+1)
__device__ float g_h[NN * NH];         // x@W1, scaled by dinv in k_finish
__device__ float g_h1[NN * NH];        // GCN output
__device__ int   g_srcsorted[NE];      // src ids grouped by dst
__device__ int   g_rank[NE];           // per-edge rank within its dst bucket

// ---------------- f32x2 helpers (FFMA2 is PTX-only) ----------------
__device__ __forceinline__ u64 pk2(float a, float b) {
    u64 r; asm("mov.b64 %0, {%1, %2};" : "=l"(r) : "f"(a), "f"(b)); return r;
}
__device__ __forceinline__ u64 dup2(float a) {
    u64 r; asm("mov.b64 %0, {%1, %1};" : "=l"(r) : "f"(a)); return r;
}
__device__ __forceinline__ u64 ffma2(u64 a, u64 b, u64 c) {
    u64 d; asm("fma.rn.f32x2 %0, %1, %2, %3;" : "=l"(d) : "l"(a), "l"(b), "l"(c)); return d;
}
__device__ __forceinline__ float2 unpk2(u64 a) {
    float2 f; asm("mov.b64 {%0, %1}, %2;" : "=f"(f.x), "=f"(f.y) : "l"(a)); return f;
}

// 4-deep pipelined CSR gather-sum: breaks the idx->feat->acc serial chain by
// batching 4 idx loads, then 4 feature loads, then one accumulate.
__device__ __forceinline__ float4 gather_sum(const float* __restrict__ feat,
                                             int start, int end, int grp, int q) {
    float4 acc = make_float4(0.f, 0.f, 0.f, 0.f);
    int j = start + grp;
    while (j + 24 < end) {
        int s0 = __ldg(&g_srcsorted[j]);
        int s1 = __ldg(&g_srcsorted[j + 8]);
        int s2 = __ldg(&g_srcsorted[j + 16]);
        int s3 = __ldg(&g_srcsorted[j + 24]);
        float4 v0 = __ldg((const float4*)&feat[s0 * NH + q * 4]);
        float4 v1 = __ldg((const float4*)&feat[s1 * NH + q * 4]);
        float4 v2 = __ldg((const float4*)&feat[s2 * NH + q * 4]);
        float4 v3 = __ldg((const float4*)&feat[s3 * NH + q * 4]);
        acc.x += (v0.x + v1.x) + (v2.x + v3.x);
        acc.y += (v0.y + v1.y) + (v2.y + v3.y);
        acc.z += (v0.z + v1.z) + (v2.z + v3.z);
        acc.w += (v0.w + v1.w) + (v2.w + v3.w);
        j += 32;
    }
    while (j < end) {
        int s = __ldg(&g_srcsorted[j]);
        float4 v = __ldg((const float4*)&feat[s * NH + q * 4]);
        acc.x += v.x; acc.y += v.y; acc.z += v.z; acc.w += v.w;
        j += 8;
    }
    return acc;
}

// ---------------- kernels ----------------

// histogram of dst + per-edge rank; 8 edges per thread
__global__ void k_count(const int* __restrict__ dst) {
    int i = blockIdx.x * blockDim.x + threadIdx.x;   // i < NOCTS
    if (i >= NOCTS) return;
    int4 d0 = ((const int4*)dst)[2 * i];
    int4 d1 = ((const int4*)dst)[2 * i + 1];
    int4 r0, r1;
    r0.x = atomicAdd(&g_cnt[d0.x], 1);
    r0.y = atomicAdd(&g_cnt[d0.y], 1);
    r0.z = atomicAdd(&g_cnt[d0.z], 1);
    r0.w = atomicAdd(&g_cnt[d0.w], 1);
    r1.x = atomicAdd(&g_cnt[d1.x], 1);
    r1.y = atomicAdd(&g_cnt[d1.y], 1);
    r1.z = atomicAdd(&g_cnt[d1.z], 1);
    r1.w = atomicAdd(&g_cnt[d1.w], 1);
    ((int4*)g_rank)[2 * i]     = r0;
    ((int4*)g_rank)[2 * i + 1] = r1;
}

// per-block exclusive scan of g_cnt chunk -> g_rowstart (block-local), totals -> g_blocksums
__global__ void k_scan_local() {
    __shared__ int s[SCAN_CHUNK];
    __shared__ int tsum[256];
    int t = threadIdx.x;
    int base = blockIdx.x * SCAN_CHUNK;
    for (int i = t; i < SCAN_CHUNK; i += 256) {
        int idx = base + i;
        s[i] = (idx < NN) ? g_cnt[idx] : 0;
    }
    __syncthreads();

    int loc[16];
    int run = 0;
#pragma unroll
    for (int i = 0; i < 16; i++) {
        run += s[t * 16 + i];
        loc[i] = run;
    }
    tsum[t] = run;
    __syncthreads();
    for (int off = 1; off < 256; off <<= 1) {
        int v = (t >= off) ? tsum[t - off] : 0;
        __syncthreads();
        tsum[t] += v;
        __syncthreads();
    }
    int ex = (t == 0) ? 0 : tsum[t - 1];
#pragma unroll
    for (int i = 0; i < 16; i++) {
        s[t * 16 + i] = ex + (i ? loc[i - 1] : 0);
    }
    __syncthreads();
    for (int i = t; i < SCAN_CHUNK; i += 256) {
        int idx = base + i;
        if (idx < NN) g_rowstart[idx] = s[i];
    }
    if (t == 0) g_blocksums[blockIdx.x] = tsum[255];
}

// atomic-free CSR scatter; 8 edges per thread; local rowstart + smem block sums
__global__ void __launch_bounds__(256)
k_scatter(const int* __restrict__ src, const int* __restrict__ dst) {
    __shared__ int sbs[SCAN_BLOCKS + 1];
    int t = threadIdx.x;
    if (t <= SCAN_BLOCKS) {
        int acc = 0;
        for (int b = 0; b < t; b++) acc += g_blocksums[b];
        sbs[t] = acc;
    }
    __syncthreads();
    int i = blockIdx.x * 256 + t;   // i < NOCTS
    if (i >= NOCTS) return;
    int4 s0 = ((const int4*)src)[2 * i];
    int4 s1 = ((const int4*)src)[2 * i + 1];
    int4 d0 = ((const int4*)dst)[2 * i];
    int4 d1 = ((const int4*)dst)[2 * i + 1];
    int4 r0 = ((const int4*)g_rank)[2 * i];
    int4 r1 = ((const int4*)g_rank)[2 * i + 1];
    int q0 = __ldg(&g_rowstart[d0.x]);
    int q1 = __ldg(&g_rowstart[d0.y]);
    int q2 = __ldg(&g_rowstart[d0.z]);
    int q3 = __ldg(&g_rowstart[d0.w]);
    int q4 = __ldg(&g_rowstart[d1.x]);
    int q5 = __ldg(&g_rowstart[d1.y]);
    int q6 = __ldg(&g_rowstart[d1.z]);
    int q7 = __ldg(&g_rowstart[d1.w]);
    g_srcsorted[q0 + sbs[d0.x >> 12] + r0.x] = s0.x;
    g_srcsorted[q1 + sbs[d0.y >> 12] + r0.y] = s0.y;
    g_srcsorted[q2 + sbs[d0.z >> 12] + r0.z] = s0.z;
    g_srcsorted[q3 + sbs[d0.w >> 12] + r0.w] = s0.w;
    g_srcsorted[q4 + sbs[d1.x >> 12] + r1.x] = s1.x;
    g_srcsorted[q5 + sbs[d1.y >> 12] + r1.y] = s1.y;
    g_srcsorted[q6 + sbs[d1.z >> 12] + r1.z] = s1.z;
    g_srcsorted[q7 + sbs[d1.w >> 12] + r1.w] = s1.w;
}

// g_h[n,:] = x[n,:] @ W1   (UNscaled fp32 — no CSR dependency; 4 nodes/thread)
__global__ void __launch_bounds__(256)
k_gemm1(const float* __restrict__ x, const float* __restrict__ W1) {
    __shared__ float sW[NF * NH];   // 16 KB
    int t = threadIdx.x;
    for (int i = t; i < NF * NH; i += 256) sW[i] = W1[i];
    __syncthreads();

    int q = t & 3;
    int slot = t >> 2;
    int base = blockIdx.x * 256;
    int n0 = base + slot;
    int n1 = n0 + 64, n2 = n0 + 128, n3 = n0 + 192;
    int c0 = min(n0, NN - 1), c1 = min(n1, NN - 1);
    int c2 = min(n2, NN - 1), c3 = min(n3, NN - 1);

    const float4* x0 = (const float4*)(x + (size_t)c0 * NF);
    const float4* x1 = (const float4*)(x + (size_t)c1 * NF);
    const float4* x2 = (const float4*)(x + (size_t)c2 * NF);
    const float4* x3 = (const float4*)(x + (size_t)c3 * NF);
    const float4* w4 = (const float4*)sW;

    u64 a00 = 0, a01 = 0, a10 = 0, a11 = 0, a20 = 0, a21 = 0, a30 = 0, a31 = 0;

#define NODE_STEP(V, A0, A1)                                        \
    do {                                                            \
        u64 dx = dup2((V).x), dy = dup2((V).y);                     \
        u64 dz = dup2((V).z), dw = dup2((V).w);                     \
        A0 = ffma2(dx, w0a, A0); A1 = ffma2(dx, w0b, A1);           \
        A0 = ffma2(dy, w1a, A0); A1 = ffma2(dy, w1b, A1);           \
        A0 = ffma2(dz, w2a, A0); A1 = ffma2(dz, w2b, A1);           \
        A0 = ffma2(dw, w3a, A0); A1 = ffma2(dw, w3b, A1);           \
    } while (0)

#pragma unroll 4
    for (int kk = 0; kk < 64; kk++) {
        float4 v0 = __ldcs(&x0[kk]);
        float4 v1 = __ldcs(&x1[kk]);
        float4 v2 = __ldcs(&x2[kk]);
        float4 v3 = __ldcs(&x3[kk]);
        int kb = kk * 16 + q;
        float4 w0 = w4[kb];
        float4 w1 = w4[kb + 4];
        float4 w2 = w4[kb + 8];
        float4 w3 = w4[kb + 12];
        u64 w0a = pk2(w0.x, w0.y), w0b = pk2(w0.z, w0.w);
        u64 w1a = pk2(w1.x, w1.y), w1b = pk2(w1.z, w1.w);
        u64 w2a = pk2(w2.x, w2.y), w2b = pk2(w2.z, w2.w);
        u64 w3a = pk2(w3.x, w3.y), w3b = pk2(w3.z, w3.w);
        NODE_STEP(v0, a00, a01);
        NODE_STEP(v1, a10, a11);
        NODE_STEP(v2, a20, a21);
        NODE_STEP(v3, a30, a31);
    }
#undef NODE_STEP

    {
        int ns[4] = {n0, n1, n2, n3};
        u64 lo[4] = {a00, a10, a20, a30};
        u64 hi[4] = {a01, a11, a21, a31};
#pragma unroll
        for (int j = 0; j < 4; j++) {
            int n = ns[j];
            if (n < NN) {
                float2 l = unpk2(lo[j]), h = unpk2(hi[j]);
                *(float4*)&g_h[n * NH + q * 4] = make_float4(l.x, l.y, h.x, h.y);
            }
        }
    }
}

// merged fixup + scale: rowfinal, dinv, and in-place g_h *= dinv (fp32).
__global__ void k_finish() {
    __shared__ int sbs[SCAN_BLOCKS];
    int t = threadIdx.x;
    if (t < SCAN_BLOCKS) sbs[t] = g_blocksums[t];
    __syncthreads();
    int i = blockIdx.x * 256 + t;   // i < NN*4
    if (i >= NN * 4) return;
    int n = i >> 2, p = i & 3;
    float dv = rsqrtf((float)(g_cnt[n] + 1));
    if (p == 0) {
        int chunk = n >> 12;
        int off = 0;
        for (int b = 0; b < chunk; b++) off += sbs[b];
        g_rowfinal[n] = g_rowstart[n] + off;
        g_dinv[n] = dv;
        if (n == 0) g_rowfinal[NN] = NE;
    }
    float4 v = *(float4*)&g_h[i * 4];
    v.x *= dv; v.y *= dv; v.z *= dv; v.w *= dv;
    *(float4*)&g_h[i * 4] = v;
}

// GCN aggregate: h1[n] = dinv[n] * (sum_{in-edges} g_h[src] + g_h[n]) + b1
// one warp per node; 8 edge-slots x 4 lanes; 4-deep pipelined gather
__global__ void k_gcn(const float* __restrict__ b1) {
    int gw = (blockIdx.x * blockDim.x + threadIdx.x) >> 5;
    int lane = threadIdx.x & 31;
    if (gw >= NN) return;
    int n = gw;
    int start = __ldg(&g_rowfinal[n]);
    int end   = __ldg(&g_rowfinal[n + 1]);
    int grp = lane >> 2, q = lane & 3;

    float4 acc = gather_sum(g_h, start, end, grp, q);
#pragma unroll
    for (int d = 4; d < 32; d <<= 1) {
        acc.x += __shfl_xor_sync(0xffffffffu, acc.x, d);
        acc.y += __shfl_xor_sync(0xffffffffu, acc.y, d);
        acc.z += __shfl_xor_sync(0xffffffffu, acc.z, d);
        acc.w += __shfl_xor_sync(0xffffffffu, acc.w, d);
    }
    if (lane < 4) {
        float4 self = *(const float4*)&g_h[n * NH + lane * 4];
        float dv = g_dinv[n];
        float4 bb = __ldg((const float4*)&b1[lane * 4]);
        float4 r;
        r.x = (acc.x + self.x) * dv + bb.x;
        r.y = (acc.y + self.y) * dv + bb.y;
        r.z = (acc.z + self.z) * dv + bb.z;
        r.w = (acc.w + self.w) * dv + bb.w;
        *(float4*)&g_h1[n * NH + lane * 4] = r;
    }
}

// SAGE: agg = mean h1[src]; out = agg@Wl + h1[n]@Wr + b2; log_softmax
__global__ void k_sage(const float* __restrict__ Wl, const float* __restrict__ Wr,
                       const float* __restrict__ b2, float* __restrict__ out) {
    __shared__ float sWl[NH * NC], sWr[NH * NC], sB2[NC];
    __shared__ float sAgg[8][16], sH1[8][16];
    int t = threadIdx.x;
    for (int i = t; i < NH * NC; i += 256) { sWl[i] = Wl[i]; sWr[i] = Wr[i]; }
    if (t < NC) sB2[t] = b2[t];
    __syncthreads();

    int wib = t >> 5, lane = t & 31;
    int n = blockIdx.x * 8 + wib;
    if (n >= NN) return;

    int start = __ldg(&g_rowfinal[n]);
    int end   = __ldg(&g_rowfinal[n + 1]);
    int grp = lane >> 2, q = lane & 3;

    float4 acc = gather_sum(g_h1, start, end, grp, q);
#pragma unroll
    for (int d = 4; d < 32; d <<= 1) {
        acc.x += __shfl_xor_sync(0xffffffffu, acc.x, d);
        acc.y += __shfl_xor_sync(0xffffffffu, acc.y, d);
        acc.z += __shfl_xor_sync(0xffffffffu, acc.z, d);
        acc.w += __shfl_xor_sync(0xffffffffu, acc.w, d);
    }
    float inv = 1.0f / fmaxf((float)(end - start), 1.0f);
    if (lane < 4) {
        float4 a;
        a.x = acc.x * inv; a.y = acc.y * inv; a.z = acc.z * inv; a.w = acc.w * inv;
        *(float4*)&sAgg[wib][lane * 4] = a;
        float4 h1v = *(const float4*)&g_h1[n * NH + lane * 4];
        *(float4*)&sH1[wib][lane * 4] = h1v;
    }
    __syncwarp();
    if (lane < 16) {
        float o = sB2[lane];
#pragma unroll
        for (int k = 0; k < 16; k++) {
            o += sAgg[wib][k] * sWl[k * NC + lane] + sH1[wib][k] * sWr[k * NC + lane];
        }
        float m = o;
#pragma unroll
        for (int d = 8; d >= 1; d >>= 1)
            m = fmaxf(m, __shfl_xor_sync(0xffffu, m, d));
        float e = __expf(o - m);
        float ssum = e;
#pragma unroll
        for (int d = 8; d >= 1; d >>= 1)
            ssum += __shfl_xor_sync(0xffffu, ssum, d);
        out[n * NC + lane] = (o - m) - __logf(ssum);
    }
}

// ---------------- launch (fork-join two-stream graph) ----------------
static cudaStream_t s2 = nullptr;
static cudaEvent_t evFork = nullptr, evScan = nullptr, evSide = nullptr;

extern "C" void kernel_launch(void* const* d_in, const int* in_sizes, int n_in,
                              void* d_out, int out_size) {
    const float* x  = (const float*)d_in[0];
    const int*   ei = (const int*)d_in[1];
    const float* W1 = (const float*)d_in[2];
    const float* b1 = (const float*)d_in[3];
    const float* Wl = (const float*)d_in[4];
    const float* Wr = (const float*)d_in[5];
    const float* b2 = (const float*)d_in[6];
    float* out = (float*)d_out;

    const int* src = ei;
    const int* dst = ei + NE;

    if (!s2) {
        cudaStreamCreateWithFlags(&s2, cudaStreamNonBlocking);
        cudaEventCreateWithFlags(&evFork, cudaEventDisableTiming);
        cudaEventCreateWithFlags(&evScan, cudaEventDisableTiming);
        cudaEventCreateWithFlags(&evSide, cudaEventDisableTiming);
    }

    void* cnt_ptr = nullptr;
    cudaGetSymbolAddress(&cnt_ptr, g_cnt);

    // fork: side stream runs gemm (no CSR deps) concurrently with CSR build
    cudaEventRecord(evFork, 0);
    cudaStreamWaitEvent(s2, evFork, 0);
    k_gemm1<<<(NN + 255) / 256, 256, 0, s2>>>(x, W1);

    // main stream: CSR build
    cudaMemsetAsync(cnt_ptr, 0, NN * sizeof(int), 0);
    k_count<<<(NOCTS + 255) / 256, 256>>>(dst);
    k_scan_local<<<SCAN_BLOCKS, 256>>>();
    cudaEventRecord(evScan, 0);
    k_scatter<<<(NOCTS + 255) / 256, 256>>>(src, dst);

    // side stream: rowfinal + dinv + in-place scale (overlaps scatter)
    cudaStreamWaitEvent(s2, evScan, 0);
    k_finish<<<(NN * 4 + 255) / 256, 256, 0, s2>>>();
    cudaEventRecord(evSide, s2);

    // join, then aggregations
    cudaStreamWaitEvent(0, evSide, 0);
    k_gcn<<<(NN * 32 + 255) / 256, 256>>>(b1);
    k_sage<<<(NN * 32 + 255) / 256, 256>>>(Wl, Wr, b2, out);
}

// round 11
// speedup vs baseline: 1.1223x; 1.0768x over previous
#include <cuda_runtime.h>
#include <cuda_bf16.h>
#include <math.h>

// Problem constants (fixed by the dataset)
#define NN 100000
#define NF 256
#define NH 16
#define NC 16
#define NE 3200000

#define CAP 128              // bucket capacity; P(Poisson(32) > 128) ~ e^-81
#define NOCTS (NE / 8)       // 400000 8-edge groups

typedef unsigned long long u64;

// ---------------- device scratch (static, allowed) ----------------
__device__ int   g_cnt[NN];             // in-degree (no self loop); zeroed by memset each launch
__device__ float g_dinv[NN];            // rsqrt(indeg+1)
__device__ float g_h[NN * NH];          // x@W1, scaled by dinv in k_finish
__device__ float g_h1[NN * NH];         // GCN output
__device__ int   g_bucket[NN * CAP];    // src ids, bucketed by dst (51.2 MB)

// ---------------- f32x2 helpers (FFMA2 is PTX-only) ----------------
__device__ __forceinline__ u64 pk2(float a, float b) {
    u64 r; asm("mov.b64 %0, {%1, %2};" : "=l"(r) : "f"(a), "f"(b)); return r;
}
__device__ __forceinline__ u64 dup2(float a) {
    u64 r; asm("mov.b64 %0, {%1, %1};" : "=l"(r) : "f"(a)); return r;
}
__device__ __forceinline__ u64 ffma2(u64 a, u64 b, u64 c) {
    u64 d; asm("fma.rn.f32x2 %0, %1, %2, %3;" : "=l"(d) : "l"(a), "l"(b), "l"(c)); return d;
}
__device__ __forceinline__ float2 unpk2(u64 a) {
    float2 f; asm("mov.b64 {%0, %1}, %2;" : "=f"(f.x), "=f"(f.y) : "l"(a)); return f;
}

// 4-deep pipelined bucket gather-sum. bucket = &g_bucket[n*CAP]; idx reads are
// coalesced (contiguous per node); feature reads are 1 wavefront per edge.
__device__ __forceinline__ float4 gather_sum(const float* __restrict__ feat,
                                             const int* __restrict__ bucket,
                                             int deg, int grp, int q) {
    float4 acc = make_float4(0.f, 0.f, 0.f, 0.f);
    int j = grp;
    while (j + 24 < deg) {
        int s0 = __ldg(&bucket[j]);
        int s1 = __ldg(&bucket[j + 8]);
        int s2 = __ldg(&bucket[j + 16]);
        int s3 = __ldg(&bucket[j + 24]);
        float4 v0 = __ldg((const float4*)&feat[s0 * NH + q * 4]);
        float4 v1 = __ldg((const float4*)&feat[s1 * NH + q * 4]);
        float4 v2 = __ldg((const float4*)&feat[s2 * NH + q * 4]);
        float4 v3 = __ldg((const float4*)&feat[s3 * NH + q * 4]);
        acc.x += (v0.x + v1.x) + (v2.x + v3.x);
        acc.y += (v0.y + v1.y) + (v2.y + v3.y);
        acc.z += (v0.z + v1.z) + (v2.z + v3.z);
        acc.w += (v0.w + v1.w) + (v2.w + v3.w);
        j += 32;
    }
    while (j < deg) {
        int s = __ldg(&bucket[j]);
        float4 v = __ldg((const float4*)&feat[s * NH + q * 4]);
        acc.x += v.x; acc.y += v.y; acc.z += v.z; acc.w += v.w;
        j += 8;
    }
    return acc;
}

// ---------------- kernels ----------------

// FUSED count + scatter: rank = atomicAdd(cnt[dst]) directly indexes the bucket.
// 2 random wavefronts per edge (atomic + store); no scan, no rowstart, no rank array.
__global__ void __launch_bounds__(256)
k_count_scatter(const int* __restrict__ src, const int* __restrict__ dst) {
    int i = blockIdx.x * 256 + threadIdx.x;   // i < NOCTS
    if (i >= NOCTS) return;
    int4 s0 = ((const int4*)src)[2 * i];
    int4 s1 = ((const int4*)src)[2 * i + 1];
    int4 d0 = ((const int4*)dst)[2 * i];
    int4 d1 = ((const int4*)dst)[2 * i + 1];
    int r0 = atomicAdd(&g_cnt[d0.x], 1);
    int r1 = atomicAdd(&g_cnt[d0.y], 1);
    int r2 = atomicAdd(&g_cnt[d0.z], 1);
    int r3 = atomicAdd(&g_cnt[d0.w], 1);
    int r4 = atomicAdd(&g_cnt[d1.x], 1);
    int r5 = atomicAdd(&g_cnt[d1.y], 1);
    int r6 = atomicAdd(&g_cnt[d1.z], 1);
    int r7 = atomicAdd(&g_cnt[d1.w], 1);
    g_bucket[d0.x * CAP + r0] = s0.x;
    g_bucket[d0.y * CAP + r1] = s0.y;
    g_bucket[d0.z * CAP + r2] = s0.z;
    g_bucket[d0.w * CAP + r3] = s0.w;
    g_bucket[d1.x * CAP + r4] = s1.x;
    g_bucket[d1.y * CAP + r5] = s1.y;
    g_bucket[d1.z * CAP + r6] = s1.z;
    g_bucket[d1.w * CAP + r7] = s1.w;
}

// g_h[n,:] = x[n,:] @ W1   (UNscaled fp32 — no graph dependency; 4 nodes/thread)
__global__ void __launch_bounds__(256)
k_gemm1(const float* __restrict__ x, const float* __restrict__ W1) {
    __shared__ float sW[NF * NH];   // 16 KB
    int t = threadIdx.x;
    for (int i = t; i < NF * NH; i += 256) sW[i] = W1[i];
    __syncthreads();

    int q = t & 3;
    int slot = t >> 2;
    int base = blockIdx.x * 256;
    int n0 = base + slot;
    int n1 = n0 + 64, n2 = n0 + 128, n3 = n0 + 192;
    int c0 = min(n0, NN - 1), c1 = min(n1, NN - 1);
    int c2 = min(n2, NN - 1), c3 = min(n3, NN - 1);

    const float4* x0 = (const float4*)(x + (size_t)c0 * NF);
    const float4* x1 = (const float4*)(x + (size_t)c1 * NF);
    const float4* x2 = (const float4*)(x + (size_t)c2 * NF);
    const float4* x3 = (const float4*)(x + (size_t)c3 * NF);
    const float4* w4 = (const float4*)sW;

    u64 a00 = 0, a01 = 0, a10 = 0, a11 = 0, a20 = 0, a21 = 0, a30 = 0, a31 = 0;

#define NODE_STEP(V, A0, A1)                                        \
    do {                                                            \
        u64 dx = dup2((V).x), dy = dup2((V).y);                     \
        u64 dz = dup2((V).z), dw = dup2((V).w);                     \
        A0 = ffma2(dx, w0a, A0); A1 = ffma2(dx, w0b, A1);           \
        A0 = ffma2(dy, w1a, A0); A1 = ffma2(dy, w1b, A1);           \
        A0 = ffma2(dz, w2a, A0); A1 = ffma2(dz, w2b, A1);           \
        A0 = ffma2(dw, w3a, A0); A1 = ffma2(dw, w3b, A1);           \
    } while (0)

#pragma unroll 4
    for (int kk = 0; kk < 64; kk++) {
        float4 v0 = __ldcs(&x0[kk]);
        float4 v1 = __ldcs(&x1[kk]);
        float4 v2 = __ldcs(&x2[kk]);
        float4 v3 = __ldcs(&x3[kk]);
        int kb = kk * 16 + q;
        float4 w0 = w4[kb];
        float4 w1 = w4[kb + 4];
        float4 w2 = w4[kb + 8];
        float4 w3 = w4[kb + 12];
        u64 w0a = pk2(w0.x, w0.y), w0b = pk2(w0.z, w0.w);
        u64 w1a = pk2(w1.x, w1.y), w1b = pk2(w1.z, w1.w);
        u64 w2a = pk2(w2.x, w2.y), w2b = pk2(w2.z, w2.w);
        u64 w3a = pk2(w3.x, w3.y), w3b = pk2(w3.z, w3.w);
        NODE_STEP(v0, a00, a01);
        NODE_STEP(v1, a10, a11);
        NODE_STEP(v2, a20, a21);
        NODE_STEP(v3, a30, a31);
    }
#undef NODE_STEP

    {
        int ns[4] = {n0, n1, n2, n3};
        u64 lo[4] = {a00, a10, a20, a30};
        u64 hi[4] = {a01, a11, a21, a31};
#pragma unroll
        for (int j = 0; j < 4; j++) {
            int n = ns[j];
            if (n < NN) {
                float2 l = unpk2(lo[j]), h = unpk2(hi[j]);
                *(float4*)&g_h[n * NH + q * 4] = make_float4(l.x, l.y, h.x, h.y);
            }
        }
    }
}

// finish: dinv + in-place g_h *= dinv (needs count + gemm)
__global__ void k_finish() {
    int i = blockIdx.x * blockDim.x + threadIdx.x;   // i < NN*4
    if (i >= NN * 4) return;
    int n = i >> 2, p = i & 3;
    float dv = rsqrtf((float)(g_cnt[n] + 1));
    if (p == 0) g_dinv[n] = dv;
    float4 v = *(float4*)&g_h[i * 4];
    v.x *= dv; v.y *= dv; v.z *= dv; v.w *= dv;
    *(float4*)&g_h[i * 4] = v;
}

// GCN aggregate: h1[n] = dinv[n] * (sum_{in-edges} g_h[src] + g_h[n]) + b1
// one warp per node; 8 edge-slots x 4 lanes; bucket rows
__global__ void k_gcn(const float* __restrict__ b1) {
    int gw = (blockIdx.x * blockDim.x + threadIdx.x) >> 5;
    int lane = threadIdx.x & 31;
    if (gw >= NN) return;
    int n = gw;
    int deg = __ldg(&g_cnt[n]);
    int grp = lane >> 2, q = lane & 3;

    float4 acc = gather_sum(g_h, &g_bucket[n * CAP], deg, grp, q);
#pragma unroll
    for (int d = 4; d < 32; d <<= 1) {
        acc.x += __shfl_xor_sync(0xffffffffu, acc.x, d);
        acc.y += __shfl_xor_sync(0xffffffffu, acc.y, d);
        acc.z += __shfl_xor_sync(0xffffffffu, acc.z, d);
        acc.w += __shfl_xor_sync(0xffffffffu, acc.w, d);
    }
    if (lane < 4) {
        float4 self = *(const float4*)&g_h[n * NH + lane * 4];
        float dv = g_dinv[n];
        float4 bb = __ldg((const float4*)&b1[lane * 4]);
        float4 r;
        r.x = (acc.x + self.x) * dv + bb.x;
        r.y = (acc.y + self.y) * dv + bb.y;
        r.z = (acc.z + self.z) * dv + bb.z;
        r.w = (acc.w + self.w) * dv + bb.w;
        *(float4*)&g_h1[n * NH + lane * 4] = r;
    }
}

// SAGE: agg = mean h1[src]; out = agg@Wl + h1[n]@Wr + b2; log_softmax
__global__ void k_sage(const float* __restrict__ Wl, const float* __restrict__ Wr,
                       const float* __restrict__ b2, float* __restrict__ out) {
    __shared__ float sWl[NH * NC], sWr[NH * NC], sB2[NC];
    __shared__ float sAgg[8][16], sH1[8][16];
    int t = threadIdx.x;
    for (int i = t; i < NH * NC; i += 256) { sWl[i] = Wl[i]; sWr[i] = Wr[i]; }
    if (t < NC) sB2[t] = b2[t];
    __syncthreads();

    int wib = t >> 5, lane = t & 31;
    int n = blockIdx.x * 8 + wib;
    if (n >= NN) return;

    int deg = __ldg(&g_cnt[n]);
    int grp = lane >> 2, q = lane & 3;

    float4 acc = gather_sum(g_h1, &g_bucket[n * CAP], deg, grp, q);
#pragma unroll
    for (int d = 4; d < 32; d <<= 1) {
        acc.x += __shfl_xor_sync(0xffffffffu, acc.x, d);
        acc.y += __shfl_xor_sync(0xffffffffu, acc.y, d);
        acc.z += __shfl_xor_sync(0xffffffffu, acc.z, d);
        acc.w += __shfl_xor_sync(0xffffffffu, acc.w, d);
    }
    float inv = 1.0f / fmaxf((float)deg, 1.0f);
    if (lane < 4) {
        float4 a;
        a.x = acc.x * inv; a.y = acc.y * inv; a.z = acc.z * inv; a.w = acc.w * inv;
        *(float4*)&sAgg[wib][lane * 4] = a;
        float4 h1v = *(const float4*)&g_h1[n * NH + lane * 4];
        *(float4*)&sH1[wib][lane * 4] = h1v;
    }
    __syncwarp();
    if (lane < 16) {
        float o = sB2[lane];
#pragma unroll
        for (int k = 0; k < 16; k++) {
            o += sAgg[wib][k] * sWl[k * NC + lane] + sH1[wib][k] * sWr[k * NC + lane];
        }
        float m = o;
#pragma unroll
        for (int d = 8; d >= 1; d >>= 1)
            m = fmaxf(m, __shfl_xor_sync(0xffffu, m, d));
        float e = __expf(o - m);
        float ssum = e;
#pragma unroll
        for (int d = 8; d >= 1; d >>= 1)
            ssum += __shfl_xor_sync(0xffffu, ssum, d);
        out[n * NC + lane] = (o - m) - __logf(ssum);
    }
}

// ---------------- launch (fork-join two-stream graph) ----------------
static cudaStream_t s2 = nullptr;
static cudaEvent_t evFork = nullptr, evGemm = nullptr;

extern "C" void kernel_launch(void* const* d_in, const int* in_sizes, int n_in,
                              void* d_out, int out_size) {
    const float* x  = (const float*)d_in[0];
    const int*   ei = (const int*)d_in[1];
    const float* W1 = (const float*)d_in[2];
    const float* b1 = (const float*)d_in[3];
    const float* Wl = (const float*)d_in[4];
    const float* Wr = (const float*)d_in[5];
    const float* b2 = (const float*)d_in[6];
    float* out = (float*)d_out;

    const int* src = ei;
    const int* dst = ei + NE;

    if (!s2) {
        cudaStreamCreateWithFlags(&s2, cudaStreamNonBlocking);
        cudaEventCreateWithFlags(&evFork, cudaEventDisableTiming);
        cudaEventCreateWithFlags(&evGemm, cudaEventDisableTiming);
    }

    void* cnt_ptr = nullptr;
    cudaGetSymbolAddress(&cnt_ptr, g_cnt);

    // fork: side stream runs gemm (no graph deps) concurrently with bucket build
    cudaEventRecord(evFork, 0);
    cudaStreamWaitEvent(s2, evFork, 0);
    k_gemm1<<<(NN + 255) / 256, 256, 0, s2>>>(x, W1);
    cudaEventRecord(evGemm, s2);

    // main stream: fused count+scatter into fixed-capacity buckets
    cudaMemsetAsync(cnt_ptr, 0, NN * sizeof(int), 0);
    k_count_scatter<<<(NOCTS + 255) / 256, 256>>>(src, dst);

    // join gemm, then finish (dinv + scale) and the two aggregation layers
    cudaStreamWaitEvent(0, evGemm, 0);
    k_finish<<<(NN * 4 + 255) / 256, 256>>>();
    k_gcn<<<(NN * 32 + 255) / 256, 256>>>(b1);
    k_sage<<<(NN * 32 + 255) / 256, 256>>>(Wl, Wr, b2, out);
}

// round 12
// speedup vs baseline: 1.3187x; 1.1750x over previous
#include <cuda_runtime.h>
#include <cuda_bf16.h>
#include <math.h>

// Problem constants (fixed by the dataset)
#define NN 100000
#define NF 256
#define NH 16
#define NC 16
#define NE 3200000

#define CAP 128              // bucket capacity; P(Poisson(32) > 128) ~ e^-81
#define NOCTS (NE / 8)       // 400000 8-edge groups

typedef unsigned long long u64;

// ---------------- device scratch (static, allowed) ----------------
__device__ int   g_cnt[NN];             // in-degree (no self loop); memset 0 each launch
__device__ float g_dinv[NN];            // rsqrt(indeg+1)
__device__ float g_h[NN * NH];          // x@W1, scaled by dinv in k_finish
__device__ float g_h1[NN * NH];         // GCN output
__device__ int   g_bucket[NN * CAP];    // src ids, bucketed by dst (51.2 MB)

// ---------------- f32x2 helpers (FFMA2 is PTX-only) ----------------
__device__ __forceinline__ u64 pk2(float a, float b) {
    u64 r; asm("mov.b64 %0, {%1, %2};" : "=l"(r) : "f"(a), "f"(b)); return r;
}
__device__ __forceinline__ u64 dup2(float a) {
    u64 r; asm("mov.b64 %0, {%1, %1};" : "=l"(r) : "f"(a)); return r;
}
__device__ __forceinline__ u64 ffma2(u64 a, u64 b, u64 c) {
    u64 d; asm("fma.rn.f32x2 %0, %1, %2, %3;" : "=l"(d) : "l"(a), "l"(b), "l"(c)); return d;
}
__device__ __forceinline__ float2 unpk2(u64 a) {
    float2 f; asm("mov.b64 {%0, %1}, %2;" : "=f"(f.x), "=f"(f.y) : "l"(a)); return f;
}

// 4-deep pipelined bucket gather-sum over 4 edge-slots (16-lane half-warp form).
// bucket = &g_bucket[n*CAP]; grp in 0..3, q in 0..3.
__device__ __forceinline__ float4 gather_sum4(const float* __restrict__ feat,
                                              const int* __restrict__ bucket,
                                              int deg, int grp, int q) {
    float4 acc = make_float4(0.f, 0.f, 0.f, 0.f);
    int j = grp;
    while (j + 12 < deg) {
        int s0 = __ldg(&bucket[j]);
        int s1 = __ldg(&bucket[j + 4]);
        int s2 = __ldg(&bucket[j + 8]);
        int s3 = __ldg(&bucket[j + 12]);
        float4 v0 = __ldg((const float4*)&feat[s0 * NH + q * 4]);
        float4 v1 = __ldg((const float4*)&feat[s1 * NH + q * 4]);
        float4 v2 = __ldg((const float4*)&feat[s2 * NH + q * 4]);
        float4 v3 = __ldg((const float4*)&feat[s3 * NH + q * 4]);
        acc.x += (v0.x + v1.x) + (v2.x + v3.x);
        acc.y += (v0.y + v1.y) + (v2.y + v3.y);
        acc.z += (v0.z + v1.z) + (v2.z + v3.z);
        acc.w += (v0.w + v1.w) + (v2.w + v3.w);
        j += 16;
    }
    while (j < deg) {
        int s = __ldg(&bucket[j]);
        float4 v = __ldg((const float4*)&feat[s * NH + q * 4]);
        acc.x += v.x; acc.y += v.y; acc.z += v.z; acc.w += v.w;
        j += 4;
    }
    return acc;
}

// reduce float4 across the 4 edge-slot groups of a 16-lane half (xor 4, 8)
#define REDHALF(A)                                               \
    A.x += __shfl_xor_sync(0xffffffffu, A.x, 4);                 \
    A.y += __shfl_xor_sync(0xffffffffu, A.y, 4);                 \
    A.z += __shfl_xor_sync(0xffffffffu, A.z, 4);                 \
    A.w += __shfl_xor_sync(0xffffffffu, A.w, 4);                 \
    A.x += __shfl_xor_sync(0xffffffffu, A.x, 8);                 \
    A.y += __shfl_xor_sync(0xffffffffu, A.y, 8);                 \
    A.z += __shfl_xor_sync(0xffffffffu, A.z, 8);                 \
    A.w += __shfl_xor_sync(0xffffffffu, A.w, 8);

// ---------------- kernels ----------------

// FUSED count + scatter: rank = atomicAdd(cnt[dst]) directly indexes the bucket.
__global__ void __launch_bounds__(256)
k_count_scatter(const int* __restrict__ src, const int* __restrict__ dst) {
    int i = blockIdx.x * 256 + threadIdx.x;   // i < NOCTS
    if (i >= NOCTS) return;
    int4 s0 = ((const int4*)src)[2 * i];
    int4 s1 = ((const int4*)src)[2 * i + 1];
    int4 d0 = ((const int4*)dst)[2 * i];
    int4 d1 = ((const int4*)dst)[2 * i + 1];
    int r0 = atomicAdd(&g_cnt[d0.x], 1);
    int r1 = atomicAdd(&g_cnt[d0.y], 1);
    int r2 = atomicAdd(&g_cnt[d0.z], 1);
    int r3 = atomicAdd(&g_cnt[d0.w], 1);
    int r4 = atomicAdd(&g_cnt[d1.x], 1);
    int r5 = atomicAdd(&g_cnt[d1.y], 1);
    int r6 = atomicAdd(&g_cnt[d1.z], 1);
    int r7 = atomicAdd(&g_cnt[d1.w], 1);
    g_bucket[d0.x * CAP + r0] = s0.x;
    g_bucket[d0.y * CAP + r1] = s0.y;
    g_bucket[d0.z * CAP + r2] = s0.z;
    g_bucket[d0.w * CAP + r3] = s0.w;
    g_bucket[d1.x * CAP + r4] = s1.x;
    g_bucket[d1.y * CAP + r5] = s1.y;
    g_bucket[d1.z * CAP + r6] = s1.z;
    g_bucket[d1.w * CAP + r7] = s1.w;
}

// g_h[n,:] = x[n,:] @ W1   (UNscaled fp32 — no graph dependency; 4 nodes/thread)
__global__ void __launch_bounds__(256)
k_gemm1(const float* __restrict__ x, const float* __restrict__ W1) {
    __shared__ float sW[NF * NH];   // 16 KB
    int t = threadIdx.x;
    for (int i = t; i < NF * NH; i += 256) sW[i] = W1[i];
    __syncthreads();

    int q = t & 3;
    int slot = t >> 2;
    int base = blockIdx.x * 256;
    int n0 = base + slot;
    int n1 = n0 + 64, n2 = n0 + 128, n3 = n0 + 192;
    int c0 = min(n0, NN - 1), c1 = min(n1, NN - 1);
    int c2 = min(n2, NN - 1), c3 = min(n3, NN - 1);

    const float4* x0 = (const float4*)(x + (size_t)c0 * NF);
    const float4* x1 = (const float4*)(x + (size_t)c1 * NF);
    const float4* x2 = (const float4*)(x + (size_t)c2 * NF);
    const float4* x3 = (const float4*)(x + (size_t)c3 * NF);
    const float4* w4 = (const float4*)sW;

    u64 a00 = 0, a01 = 0, a10 = 0, a11 = 0, a20 = 0, a21 = 0, a30 = 0, a31 = 0;

#define NODE_STEP(V, A0, A1)                                        \
    do {                                                            \
        u64 dx = dup2((V).x), dy = dup2((V).y);                     \
        u64 dz = dup2((V).z), dw = dup2((V).w);                     \
        A0 = ffma2(dx, w0a, A0); A1 = ffma2(dx, w0b, A1);           \
        A0 = ffma2(dy, w1a, A0); A1 = ffma2(dy, w1b, A1);           \
        A0 = ffma2(dz, w2a, A0); A1 = ffma2(dz, w2b, A1);           \
        A0 = ffma2(dw, w3a, A0); A1 = ffma2(dw, w3b, A1);           \
    } while (0)

#pragma unroll 4
    for (int kk = 0; kk < 64; kk++) {
        float4 v0 = __ldcs(&x0[kk]);
        float4 v1 = __ldcs(&x1[kk]);
        float4 v2 = __ldcs(&x2[kk]);
        float4 v3 = __ldcs(&x3[kk]);
        int kb = kk * 16 + q;
        float4 w0 = w4[kb];
        float4 w1 = w4[kb + 4];
        float4 w2 = w4[kb + 8];
        float4 w3 = w4[kb + 12];
        u64 w0a = pk2(w0.x, w0.y), w0b = pk2(w0.z, w0.w);
        u64 w1a = pk2(w1.x, w1.y), w1b = pk2(w1.z, w1.w);
        u64 w2a = pk2(w2.x, w2.y), w2b = pk2(w2.z, w2.w);
        u64 w3a = pk2(w3.x, w3.y), w3b = pk2(w3.z, w3.w);
        NODE_STEP(v0, a00, a01);
        NODE_STEP(v1, a10, a11);
        NODE_STEP(v2, a20, a21);
        NODE_STEP(v3, a30, a31);
    }
#undef NODE_STEP

    {
        int ns[4] = {n0, n1, n2, n3};
        u64 lo[4] = {a00, a10, a20, a30};
        u64 hi[4] = {a01, a11, a21, a31};
#pragma unroll
        for (int j = 0; j < 4; j++) {
            int n = ns[j];
            if (n < NN) {
                float2 l = unpk2(lo[j]), h = unpk2(hi[j]);
                *(float4*)&g_h[n * NH + q * 4] = make_float4(l.x, l.y, h.x, h.y);
            }
        }
    }
}

// finish: dinv + in-place g_h *= dinv (needs count + gemm)
__global__ void k_finish() {
    int i = blockIdx.x * blockDim.x + threadIdx.x;   // i < NN*4
    if (i >= NN * 4) return;
    int n = i >> 2, p = i & 3;
    float dv = rsqrtf((float)(g_cnt[n] + 1));
    if (p == 0) g_dinv[n] = dv;
    float4 v = *(float4*)&g_h[i * 4];
    v.x *= dv; v.y *= dv; v.z *= dv; v.w *= dv;
    *(float4*)&g_h[i * 4] = v;
}

// GCN aggregate: 2 nodes per warp; each node = 16 lanes (4 slots x 4 q-lanes)
__global__ void __launch_bounds__(256)
k_gcn(const float* __restrict__ b1) {
    int w = (blockIdx.x * blockDim.x + threadIdx.x) >> 5;   // warp id
    int lane = threadIdx.x & 31;
    int half = lane >> 4;        // node select within warp
    int hl = lane & 15;          // lane within half
    int grp = hl >> 2, q = hl & 3;
    int n = w * 2 + half;
    if (n >= NN) return;

    int deg = __ldg(&g_cnt[n]);
    float4 acc = gather_sum4(g_h, &g_bucket[n * CAP], deg, grp, q);
    REDHALF(acc);

    if (hl < 4) {   // hl == q here
        float4 self = *(const float4*)&g_h[n * NH + hl * 4];
        float dv = g_dinv[n];
        float4 bb = __ldg((const float4*)&b1[hl * 4]);
        float4 r;
        r.x = (acc.x + self.x) * dv + bb.x;
        r.y = (acc.y + self.y) * dv + bb.y;
        r.z = (acc.z + self.z) * dv + bb.z;
        r.w = (acc.w + self.w) * dv + bb.w;
        *(float4*)&g_h1[n * NH + hl * 4] = r;
    }
}

// SAGE: 2 nodes per warp; gather + tiny GEMM + log_softmax, all 32 lanes active
__global__ void __launch_bounds__(256)
k_sage(const float* __restrict__ Wl, const float* __restrict__ Wr,
       const float* __restrict__ b2, float* __restrict__ out) {
    __shared__ float sWl[NH * NC], sWr[NH * NC], sB2[NC];
    __shared__ float sAgg[16][16], sH1[16][16];
    int t = threadIdx.x;
    for (int i = t; i < NH * NC; i += 256) { sWl[i] = Wl[i]; sWr[i] = Wr[i]; }
    if (t < NC) sB2[t] = b2[t];
    __syncthreads();

    int lane = t & 31;
    int half = lane >> 4;
    int hl = lane & 15;
    int grp = hl >> 2, q = hl & 3;
    int nb = ((t >> 5) << 1) + half;             // node slot within block (0..15)
    int n = blockIdx.x * 16 + nb;
    if (n >= NN) return;

    int deg = __ldg(&g_cnt[n]);
    float4 acc = gather_sum4(g_h1, &g_bucket[n * CAP], deg, grp, q);
    REDHALF(acc);

    if (hl < 4) {   // hl == q
        float inv = 1.0f / fmaxf((float)deg, 1.0f);
        float4 a;
        a.x = acc.x * inv; a.y = acc.y * inv; a.z = acc.z * inv; a.w = acc.w * inv;
        *(float4*)&sAgg[nb][hl * 4] = a;
        float4 h1v = *(const float4*)&g_h1[n * NH + hl * 4];
        *(float4*)&sH1[nb][hl * 4] = h1v;
    }
    __syncwarp();

    // all 32 lanes: each half computes its node's 16 outputs (c = hl)
    float o = sB2[hl];
#pragma unroll
    for (int k = 0; k < 16; k++) {
        o += sAgg[nb][k] * sWl[k * NC + hl] + sH1[nb][k] * sWr[k * NC + hl];
    }
    // log_softmax over the 16 lanes of this half (xor < 16 stays in-half)
    float m = o;
#pragma unroll
    for (int d = 8; d >= 1; d >>= 1)
        m = fmaxf(m, __shfl_xor_sync(0xffffffffu, m, d));
    float e = __expf(o - m);
    float ssum = e;
#pragma unroll
    for (int d = 8; d >= 1; d >>= 1)
        ssum += __shfl_xor_sync(0xffffffffu, ssum, d);
    out[n * NC + hl] = (o - m) - __logf(ssum);
}

// ---------------- launch (fork-join two-stream graph) ----------------
static cudaStream_t s2 = nullptr;
static cudaEvent_t evFork = nullptr, evGemm = nullptr;

extern "C" void kernel_launch(void* const* d_in, const int* in_sizes, int n_in,
                              void* d_out, int out_size) {
    const float* x  = (const float*)d_in[0];
    const int*   ei = (const int*)d_in[1];
    const float* W1 = (const float*)d_in[2];
    const float* b1 = (const float*)d_in[3];
    const float* Wl = (const float*)d_in[4];
    const float* Wr = (const float*)d_in[5];
    const float* b2 = (const float*)d_in[6];
    float* out = (float*)d_out;

    const int* src = ei;
    const int* dst = ei + NE;

    if (!s2) {
        cudaStreamCreateWithFlags(&s2, cudaStreamNonBlocking);
        cudaEventCreateWithFlags(&evFork, cudaEventDisableTiming);
        cudaEventCreateWithFlags(&evGemm, cudaEventDisableTiming);
    }

    void* cnt_ptr = nullptr;
    cudaGetSymbolAddress(&cnt_ptr, g_cnt);

    // fork: side stream runs gemm (no graph deps) concurrently with bucket build
    cudaEventRecord(evFork, 0);
    cudaStreamWaitEvent(s2, evFork, 0);
    k_gemm1<<<(NN + 255) / 256, 256, 0, s2>>>(x, W1);
    cudaEventRecord(evGemm, s2);

    // main stream: fused count+scatter into fixed-capacity buckets
    cudaMemsetAsync(cnt_ptr, 0, NN * sizeof(int), 0);
    k_count_scatter<<<(NOCTS + 255) / 256, 256>>>(src, dst);

    // join gemm, then finish (dinv + scale) and the two aggregation layers
    cudaStreamWaitEvent(0, evGemm, 0);
    k_finish<<<(NN * 4 + 255) / 256, 256>>>();
    k_gcn<<<(NN / 2 * 32 + 255) / 256, 256>>>(b1);          // 2 nodes/warp
    k_sage<<<(NN + 15) / 16, 256>>>(Wl, Wr, b2, out);       // 16 nodes/block
}

// round 13
// speedup vs baseline: 1.3193x; 1.0005x over previous
#include <cuda_runtime.h>
#include <cuda_bf16.h>
#include <math.h>

// Problem constants (fixed by the dataset)
#define NN 100000
#define NF 256
#define NH 16
#define NC 16
#define NE 3200000

#define CAP 128              // bucket capacity; P(Poisson(32) > 128) ~ e^-81
#define NOCTS (NE / 8)       // 400000 8-edge groups

typedef unsigned long long u64;

// ---------------- device scratch (static, allowed) ----------------
__device__ int   g_cnt[NN];             // in-degree (no self loop); memset 0 each launch
__device__ float g_dinv[NN];            // rsqrt(indeg+1)
__device__ float g_h[NN * NH];          // x@W1, scaled by dinv in k_finish
__device__ float g_h1[NN * NH];         // GCN output
__device__ int   g_bucket[NN * CAP];    // src ids, bucketed by dst (51.2 MB)

// ---------------- f32x2 helpers (FFMA2 is PTX-only) ----------------
__device__ __forceinline__ u64 pk2(float a, float b) {
    u64 r; asm("mov.b64 %0, {%1, %2};" : "=l"(r) : "f"(a), "f"(b)); return r;
}
__device__ __forceinline__ u64 dup2(float a) {
    u64 r; asm("mov.b64 %0, {%1, %1};" : "=l"(r) : "f"(a)); return r;
}
__device__ __forceinline__ u64 ffma2(u64 a, u64 b, u64 c) {
    u64 d; asm("fma.rn.f32x2 %0, %1, %2, %3;" : "=l"(d) : "l"(a), "l"(b), "l"(c)); return d;
}
__device__ __forceinline__ float2 unpk2(u64 a) {
    float2 f; asm("mov.b64 {%0, %1}, %2;" : "=f"(f.x), "=f"(f.y) : "l"(a)); return f;
}

// Bucket gather-sum over 16-edge batches; ONE int4 LDG fetches this grp's 4
// indices (contiguous, 16B-aligned), then 4 independent float4 feature loads.
// bucket = &g_bucket[n*CAP]; grp in 0..3, q in 0..3.
__device__ __forceinline__ float4 gather_sum4(const float* __restrict__ feat,
                                              const int* __restrict__ bucket,
                                              int deg, int grp, int q) {
    float4 acc = make_float4(0.f, 0.f, 0.f, 0.f);
    int j = 0;
    for (; j + 16 <= deg; j += 16) {
        int4 ss = __ldg((const int4*)&bucket[j + grp * 4]);
        float4 v0 = __ldg((const float4*)&feat[ss.x * NH + q * 4]);
        float4 v1 = __ldg((const float4*)&feat[ss.y * NH + q * 4]);
        float4 v2 = __ldg((const float4*)&feat[ss.z * NH + q * 4]);
        float4 v3 = __ldg((const float4*)&feat[ss.w * NH + q * 4]);
        acc.x += (v0.x + v1.x) + (v2.x + v3.x);
        acc.y += (v0.y + v1.y) + (v2.y + v3.y);
        acc.z += (v0.z + v1.z) + (v2.z + v3.z);
        acc.w += (v0.w + v1.w) + (v2.w + v3.w);
    }
    for (int e = j + grp; e < deg; e += 4) {
        int s = __ldg(&bucket[e]);
        float4 v = __ldg((const float4*)&feat[s * NH + q * 4]);
        acc.x += v.x; acc.y += v.y; acc.z += v.z; acc.w += v.w;
    }
    return acc;
}

// reduce float4 across the 4 edge-slot groups of a 16-lane half (xor 4, 8)
#define REDHALF(A)                                               \
    A.x += __shfl_xor_sync(0xffffffffu, A.x, 4);                 \
    A.y += __shfl_xor_sync(0xffffffffu, A.y, 4);                 \
    A.z += __shfl_xor_sync(0xffffffffu, A.z, 4);                 \
    A.w += __shfl_xor_sync(0xffffffffu, A.w, 4);                 \
    A.x += __shfl_xor_sync(0xffffffffu, A.x, 8);                 \
    A.y += __shfl_xor_sync(0xffffffffu, A.y, 8);                 \
    A.z += __shfl_xor_sync(0xffffffffu, A.z, 8);                 \
    A.w += __shfl_xor_sync(0xffffffffu, A.w, 8);

// ---------------- kernels ----------------

// FUSED count + scatter: rank = atomicAdd(cnt[dst]) directly indexes the bucket.
__global__ void __launch_bounds__(256)
k_count_scatter(const int* __restrict__ src, const int* __restrict__ dst) {
    int i = blockIdx.x * 256 + threadIdx.x;   // i < NOCTS
    if (i >= NOCTS) return;
    int4 s0 = ((const int4*)src)[2 * i];
    int4 s1 = ((const int4*)src)[2 * i + 1];
    int4 d0 = ((const int4*)dst)[2 * i];
    int4 d1 = ((const int4*)dst)[2 * i + 1];
    int r0 = atomicAdd(&g_cnt[d0.x], 1);
    int r1 = atomicAdd(&g_cnt[d0.y], 1);
    int r2 = atomicAdd(&g_cnt[d0.z], 1);
    int r3 = atomicAdd(&g_cnt[d0.w], 1);
    int r4 = atomicAdd(&g_cnt[d1.x], 1);
    int r5 = atomicAdd(&g_cnt[d1.y], 1);
    int r6 = atomicAdd(&g_cnt[d1.z], 1);
    int r7 = atomicAdd(&g_cnt[d1.w], 1);
    g_bucket[d0.x * CAP + r0] = s0.x;
    g_bucket[d0.y * CAP + r1] = s0.y;
    g_bucket[d0.z * CAP + r2] = s0.z;
    g_bucket[d0.w * CAP + r3] = s0.w;
    g_bucket[d1.x * CAP + r4] = s1.x;
    g_bucket[d1.y * CAP + r5] = s1.y;
    g_bucket[d1.z * CAP + r6] = s1.z;
    g_bucket[d1.w * CAP + r7] = s1.w;
}

// g_h[n,:] = x[n,:] @ W1   (UNscaled fp32 — no graph dependency; 4 nodes/thread)
__global__ void __launch_bounds__(256)
k_gemm1(const float* __restrict__ x, const float* __restrict__ W1) {
    __shared__ float sW[NF * NH];   // 16 KB
    int t = threadIdx.x;
    for (int i = t; i < NF * NH; i += 256) sW[i] = W1[i];
    __syncthreads();

    int q = t & 3;
    int slot = t >> 2;
    int base = blockIdx.x * 256;
    int n0 = base + slot;
    int n1 = n0 + 64, n2 = n0 + 128, n3 = n0 + 192;
    int c0 = min(n0, NN - 1), c1 = min(n1, NN - 1);
    int c2 = min(n2, NN - 1), c3 = min(n3, NN - 1);

    const float4* x0 = (const float4*)(x + (size_t)c0 * NF);
    const float4* x1 = (const float4*)(x + (size_t)c1 * NF);
    const float4* x2 = (const float4*)(x + (size_t)c2 * NF);
    const float4* x3 = (const float4*)(x + (size_t)c3 * NF);
    const float4* w4 = (const float4*)sW;

    u64 a00 = 0, a01 = 0, a10 = 0, a11 = 0, a20 = 0, a21 = 0, a30 = 0, a31 = 0;

#define NODE_STEP(V, A0, A1)                                        \
    do {                                                            \
        u64 dx = dup2((V).x), dy = dup2((V).y);                     \
        u64 dz = dup2((V).z), dw = dup2((V).w);                     \
        A0 = ffma2(dx, w0a, A0); A1 = ffma2(dx, w0b, A1);           \
        A0 = ffma2(dy, w1a, A0); A1 = ffma2(dy, w1b, A1);           \
        A0 = ffma2(dz, w2a, A0); A1 = ffma2(dz, w2b, A1);           \
        A0 = ffma2(dw, w3a, A0); A1 = ffma2(dw, w3b, A1);           \
    } while (0)

#pragma unroll 4
    for (int kk = 0; kk < 64; kk++) {
        float4 v0 = __ldcs(&x0[kk]);
        float4 v1 = __ldcs(&x1[kk]);
        float4 v2 = __ldcs(&x2[kk]);
        float4 v3 = __ldcs(&x3[kk]);
        int kb = kk * 16 + q;
        float4 w0 = w4[kb];
        float4 w1 = w4[kb + 4];
        float4 w2 = w4[kb + 8];
        float4 w3 = w4[kb + 12];
        u64 w0a = pk2(w0.x, w0.y), w0b = pk2(w0.z, w0.w);
        u64 w1a = pk2(w1.x, w1.y), w1b = pk2(w1.z, w1.w);
        u64 w2a = pk2(w2.x, w2.y), w2b = pk2(w2.z, w2.w);
        u64 w3a = pk2(w3.x, w3.y), w3b = pk2(w3.z, w3.w);
        NODE_STEP(v0, a00, a01);
        NODE_STEP(v1, a10, a11);
        NODE_STEP(v2, a20, a21);
        NODE_STEP(v3, a30, a31);
    }
#undef NODE_STEP

    {
        int ns[4] = {n0, n1, n2, n3};
        u64 lo[4] = {a00, a10, a20, a30};
        u64 hi[4] = {a01, a11, a21, a31};
#pragma unroll
        for (int j = 0; j < 4; j++) {
            int n = ns[j];
            if (n < NN) {
                float2 l = unpk2(lo[j]), h = unpk2(hi[j]);
                *(float4*)&g_h[n * NH + q * 4] = make_float4(l.x, l.y, h.x, h.y);
            }
        }
    }
}

// finish: dinv + in-place g_h *= dinv (needs count + gemm)
__global__ void k_finish() {
    int i = blockIdx.x * blockDim.x + threadIdx.x;   // i < NN*4
    if (i >= NN * 4) return;
    int n = i >> 2, p = i & 3;
    float dv = rsqrtf((float)(g_cnt[n] + 1));
    if (p == 0) g_dinv[n] = dv;
    float4 v = *(float4*)&g_h[i * 4];
    v.x *= dv; v.y *= dv; v.z *= dv; v.w *= dv;
    *(float4*)&g_h[i * 4] = v;
}

// GCN aggregate: 2 nodes per warp; each node = 16 lanes (4 slots x 4 q-lanes)
__global__ void __launch_bounds__(256)
k_gcn(const float* __restrict__ b1) {
    int w = (blockIdx.x * blockDim.x + threadIdx.x) >> 5;   // warp id
    int lane = threadIdx.x & 31;
    int half = lane >> 4;        // node select within warp
    int hl = lane & 15;          // lane within half
    int grp = hl >> 2, q = hl & 3;
    int n = w * 2 + half;
    if (n >= NN) return;

    int deg = __ldg(&g_cnt[n]);
    float4 acc = gather_sum4(g_h, &g_bucket[n * CAP], deg, grp, q);
    REDHALF(acc);

    if (hl < 4) {   // hl == q here
        float4 self = *(const float4*)&g_h[n * NH + hl * 4];
        float dv = g_dinv[n];
        float4 bb = __ldg((const float4*)&b1[hl * 4]);
        float4 r;
        r.x = (acc.x + self.x) * dv + bb.x;
        r.y = (acc.y + self.y) * dv + bb.y;
        r.z = (acc.z + self.z) * dv + bb.z;
        r.w = (acc.w + self.w) * dv + bb.w;
        *(float4*)&g_h1[n * NH + hl * 4] = r;
    }
}

// SAGE: 2 nodes per warp; gather + tiny GEMM + log_softmax, all 32 lanes active
__global__ void __launch_bounds__(256)
k_sage(const float* __restrict__ Wl, const float* __restrict__ Wr,
       const float* __restrict__ b2, float* __restrict__ out) {
    __shared__ float sWl[NH * NC], sWr[NH * NC], sB2[NC];
    __shared__ float sAgg[16][16], sH1[16][16];
    int t = threadIdx.x;
    for (int i = t; i < NH * NC; i += 256) { sWl[i] = Wl[i]; sWr[i] = Wr[i]; }
    if (t < NC) sB2[t] = b2[t];
    __syncthreads();

    int lane = t & 31;
    int half = lane >> 4;
    int hl = lane & 15;
    int grp = hl >> 2, q = hl & 3;
    int nb = ((t >> 5) << 1) + half;             // node slot within block (0..15)
    int n = blockIdx.x * 16 + nb;
    if (n >= NN) return;

    int deg = __ldg(&g_cnt[n]);
    float4 acc = gather_sum4(g_h1, &g_bucket[n * CAP], deg, grp, q);
    REDHALF(acc);

    if (hl < 4) {   // hl == q
        float inv = 1.0f / fmaxf((float)deg, 1.0f);
        float4 a;
        a.x = acc.x * inv; a.y = acc.y * inv; a.z = acc.z * inv; a.w = acc.w * inv;
        *(float4*)&sAgg[nb][hl * 4] = a;
        float4 h1v = *(const float4*)&g_h1[n * NH + hl * 4];
        *(float4*)&sH1[nb][hl * 4] = h1v;
    }
    __syncwarp();

    // all 32 lanes: each half computes its node's 16 outputs (c = hl)
    float o = sB2[hl];
#pragma unroll
    for (int k = 0; k < 16; k++) {
        o += sAgg[nb][k] * sWl[k * NC + hl] + sH1[nb][k] * sWr[k * NC + hl];
    }
    // log_softmax over the 16 lanes of this half (xor < 16 stays in-half)
    float m = o;
#pragma unroll
    for (int d = 8; d >= 1; d >>= 1)
        m = fmaxf(m, __shfl_xor_sync(0xffffffffu, m, d));
    float e = __expf(o - m);
    float ssum = e;
#pragma unroll
    for (int d = 8; d >= 1; d >>= 1)
        ssum += __shfl_xor_sync(0xffffffffu, ssum, d);
    out[n * NC + hl] = (o - m) - __logf(ssum);
}

// ---------------- launch (fork-join two-stream graph) ----------------
static cudaStream_t s2 = nullptr;
static cudaEvent_t evFork = nullptr, evGemm = nullptr;

extern "C" void kernel_launch(void* const* d_in, const int* in_sizes, int n_in,
                              void* d_out, int out_size) {
    const float* x  = (const float*)d_in[0];
    const int*   ei = (const int*)d_in[1];
    const float* W1 = (const float*)d_in[2];
    const float* b1 = (const float*)d_in[3];
    const float* Wl = (const float*)d_in[4];
    const float* Wr = (const float*)d_in[5];
    const float* b2 = (const float*)d_in[6];
    float* out = (float*)d_out;

    const int* src = ei;
    const int* dst = ei + NE;

    if (!s2) {
        cudaStreamCreateWithFlags(&s2, cudaStreamNonBlocking);
        cudaEventCreateWithFlags(&evFork, cudaEventDisableTiming);
        cudaEventCreateWithFlags(&evGemm, cudaEventDisableTiming);
    }

    void* cnt_ptr = nullptr;
    cudaGetSymbolAddress(&cnt_ptr, g_cnt);

    // fork: side stream runs gemm (no graph deps) concurrently with bucket build
    cudaEventRecord(evFork, 0);
    cudaStreamWaitEvent(s2, evFork, 0);
    k_gemm1<<<(NN + 255) / 256, 256, 0, s2>>>(x, W1);
    cudaEventRecord(evGemm, s2);

    // main stream: fused count+scatter into fixed-capacity buckets
    cudaMemsetAsync(cnt_ptr, 0, NN * sizeof(int), 0);
    k_count_scatter<<<(NOCTS + 255) / 256, 256>>>(src, dst);

    // join gemm, then finish (dinv + scale) and the two aggregation layers
    cudaStreamWaitEvent(0, evGemm, 0);
    k_finish<<<(NN * 4 + 255) / 256, 256>>>();
    k_gcn<<<(NN / 2 * 32 + 255) / 256, 256>>>(b1);          // 2 nodes/warp
    k_sage<<<(NN + 15) / 16, 256>>>(Wl, Wr, b2, out);       // 16 nodes/block
}